// round 1
// baseline (speedup 1.0000x reference)
#include <cuda_runtime.h>
#include <math.h>

#define BB 4
#define SS 2048
#define HH 512
#define NH 8
#define DKK 64
#define NEG_INF -1e30f

// ---------------- scratch (device globals; no allocation allowed) ----------
__device__ float g_xn[BB * SS * HH];          // layernorm output (B*S, H)
__device__ float g_q[BB * NH * SS * DKK];     // (b,n,s,d)
__device__ float g_k[BB * NH * SS * DKK];
__device__ float g_v[BB * NH * SS * DKK];
__device__ float g_attn[BB * SS * HH];        // (b,s, n*DK+d)

// ---------------- 1) LayerNorm ----------------------------------------------
__global__ void ln_kernel(const float* __restrict__ x,
                          const float* __restrict__ gamma,
                          const float* __restrict__ beta) {
    int row = blockIdx.x;                 // 0 .. B*S-1
    const float* xr = x + (size_t)row * HH;
    int t = threadIdx.x;                  // 256 threads
    float a = xr[t];
    float b = xr[t + 256];
    float s  = a + b;
    float sq = a * a + b * b;
    __shared__ float ssum[8], ssq[8];
    for (int o = 16; o > 0; o >>= 1) {
        s  += __shfl_xor_sync(0xffffffffu, s,  o);
        sq += __shfl_xor_sync(0xffffffffu, sq, o);
    }
    if ((t & 31) == 0) { ssum[t >> 5] = s; ssq[t >> 5] = sq; }
    __syncthreads();
    float tot = 0.f, totq = 0.f;
#pragma unroll
    for (int i = 0; i < 8; i++) { tot += ssum[i]; totq += ssq[i]; }
    float mu  = tot * (1.0f / HH);
    float var = totq * (1.0f / HH) - mu * mu;
    float inv = rsqrtf(var + 1e-5f);
    float* dst = g_xn + (size_t)row * HH;
    dst[t]       = (a - mu) * inv * gamma[t]       + beta[t];
    dst[t + 256] = (b - mu) * inv * gamma[t + 256] + beta[t + 256];
}

// ---------------- 2) QKV projection GEMMs -----------------------------------
// For each (which in {q,k,v}, b, n): C[S x 64] = XN_b[S x 512] @ W_n[512 x 64]
// grid: (S/64 = 32, 3*B*NH = 96), block 256 (16x16 threads, 4x4 micro-tile)
__global__ __launch_bounds__(256)
void qkv_kernel(const float* __restrict__ Wq,
                const float* __restrict__ Wk,
                const float* __restrict__ Wv) {
    int mt    = blockIdx.x;
    int which = blockIdx.y / (BB * NH);
    int bn    = blockIdx.y % (BB * NH);
    int b = bn / NH, n = bn % NH;

    const float* W = (which == 0 ? Wq : (which == 1 ? Wk : Wv)) + (size_t)n * HH * DKK;
    float* Cout    = (which == 0 ? g_q : (which == 1 ? g_k : g_v)) + (size_t)bn * SS * DKK;
    const float* Arow = g_xn + (size_t)b * SS * HH + (size_t)mt * 64 * HH;

    __shared__ float As[32][68];   // [k][m], padded, 16B-aligned rows
    __shared__ float Bs[32][64];   // [k][n]

    int t  = threadIdx.x;
    int tx = t & 15, ty = t >> 4;
    float acc[4][4] = {};

    for (int k0 = 0; k0 < HH; k0 += 32) {
        // load A tile: 64x32, transposed into As[k][m]
        {
            int idx = t * 8;
            int m   = idx >> 5;
            int kk  = idx & 31;
            const float4* src = (const float4*)(Arow + (size_t)m * HH + k0 + kk);
            float4 u0 = src[0], u1 = src[1];
            As[kk + 0][m] = u0.x; As[kk + 1][m] = u0.y;
            As[kk + 2][m] = u0.z; As[kk + 3][m] = u0.w;
            As[kk + 4][m] = u1.x; As[kk + 5][m] = u1.y;
            As[kk + 6][m] = u1.z; As[kk + 7][m] = u1.w;
        }
        // load B tile: 32x64
        {
            int idx = t * 8;
            int kk  = idx >> 6;
            int nn  = idx & 63;
            const float4* src = (const float4*)(W + (size_t)(k0 + kk) * DKK + nn);
            float4* dst = (float4*)&Bs[kk][nn];
            dst[0] = src[0];
            dst[1] = src[1];
        }
        __syncthreads();
#pragma unroll
        for (int kk = 0; kk < 32; kk++) {
            float4 av = *(const float4*)&As[kk][ty * 4];
            float4 bv = *(const float4*)&Bs[kk][tx * 4];
            float a[4] = {av.x, av.y, av.z, av.w};
            float bb2[4] = {bv.x, bv.y, bv.z, bv.w};
#pragma unroll
            for (int i = 0; i < 4; i++)
#pragma unroll
                for (int j = 0; j < 4; j++)
                    acc[i][j] += a[i] * bb2[j];
        }
        __syncthreads();
    }
#pragma unroll
    for (int i = 0; i < 4; i++) {
        int r = mt * 64 + ty * 4 + i;
#pragma unroll
        for (int j = 0; j < 4; j++)
            Cout[(size_t)r * DKK + tx * 4 + j] = acc[i][j];
    }
}

// ---------------- 3) masked flash attention (fp32) --------------------------
// grid: (S/64 = 32 q-tiles, B*NH = 32), block 64 threads (1 query row each)
__global__ __launch_bounds__(64)
void attn_kernel(const int* __restrict__ mask) {
    int bn = blockIdx.y;
    int b  = bn >> 3;
    int n  = bn & 7;
    int qi = threadIdx.x;
    int qrow = blockIdx.x * 64 + qi;

    __shared__ float Ks[64 * 64];
    __shared__ float Vs[64 * 64];
    __shared__ int   msk[64];

    // q row into registers
    float qreg[64];
    {
        const float4* q4 = (const float4*)(g_q + ((size_t)bn * SS + qrow) * DKK);
#pragma unroll
        for (int i = 0; i < 16; i++) {
            float4 u = q4[i];
            qreg[4 * i + 0] = u.x; qreg[4 * i + 1] = u.y;
            qreg[4 * i + 2] = u.z; qreg[4 * i + 3] = u.w;
        }
    }
    float o[64];
#pragma unroll
    for (int d = 0; d < 64; d++) o[d] = 0.f;
    float mmax = NEG_INF, l = 0.f;

    for (int kt = 0; kt < SS / 64; kt++) {
        const float4* ksrc = (const float4*)(g_k + ((size_t)bn * SS + kt * 64) * DKK);
        const float4* vsrc = (const float4*)(g_v + ((size_t)bn * SS + kt * 64) * DKK);
        float4* kd = (float4*)Ks;
        float4* vd = (float4*)Vs;
#pragma unroll
        for (int i = 0; i < 16; i++) {
            kd[qi + 64 * i] = ksrc[qi + 64 * i];
            vd[qi + 64 * i] = vsrc[qi + 64 * i];
        }
        msk[qi] = mask[(size_t)b * SS + kt * 64 + qi];
        __syncthreads();

#pragma unroll 1
        for (int jc = 0; jc < 4; jc++) {
            float sc[16];
            float tmax = NEG_INF;
#pragma unroll
            for (int jj = 0; jj < 16; jj++) {
                int j = jc * 16 + jj;
                float sval;
                if (msk[j]) {
                    float dot = 0.f;
                    const float4* kr = (const float4*)&Ks[j * 64];
#pragma unroll
                    for (int i = 0; i < 16; i++) {
                        float4 u = kr[i];
                        dot += qreg[4 * i + 0] * u.x + qreg[4 * i + 1] * u.y
                             + qreg[4 * i + 2] * u.z + qreg[4 * i + 3] * u.w;
                    }
                    sval = dot * 0.125f;   // 1/sqrt(64)
                } else {
                    sval = NEG_INF;
                }
                sc[jj] = sval;
                tmax = fmaxf(tmax, sval);
            }
            if (tmax > mmax) {
                float mnew  = tmax;
                float scale = __expf(mmax - mnew);
                l *= scale;
#pragma unroll
                for (int d = 0; d < 64; d++) o[d] *= scale;
                mmax = mnew;
            }
#pragma unroll
            for (int jj = 0; jj < 16; jj++) {
                int j = jc * 16 + jj;
                float p = __expf(sc[jj] - mmax);
                l += p;
                const float4* vr = (const float4*)&Vs[j * 64];
#pragma unroll
                for (int i = 0; i < 16; i++) {
                    float4 u = vr[i];
                    o[4 * i + 0] += p * u.x; o[4 * i + 1] += p * u.y;
                    o[4 * i + 2] += p * u.z; o[4 * i + 3] += p * u.w;
                }
            }
        }
        __syncthreads();
    }

    float inv = (l > 0.f) ? (1.f / l) : 0.f;
    float* dst = g_attn + ((size_t)b * SS + qrow) * HH + n * DKK;
#pragma unroll
    for (int i = 0; i < 16; i++) {
        float4 u;
        u.x = o[4 * i + 0] * inv; u.y = o[4 * i + 1] * inv;
        u.z = o[4 * i + 2] * inv; u.w = o[4 * i + 3] * inv;
        ((float4*)dst)[i] = u;
    }
}

// ---------------- 4) output projection + residual + row mask ----------------
// out[8192 x 512] = (g_attn @ Wo + g_xn) * mf[row]
// grid: (512/64 = 8 n-tiles, 8192/64 = 128 m-tiles), block 256
__global__ __launch_bounds__(256)
void outproj_kernel(const float* __restrict__ Wo,
                    const int* __restrict__ mask,
                    float* __restrict__ out) {
    int nt = blockIdx.x;
    int mt = blockIdx.y;
    const float* Arow = g_attn + (size_t)mt * 64 * HH;

    __shared__ float As[32][68];
    __shared__ float Bs[32][64];

    int t  = threadIdx.x;
    int tx = t & 15, ty = t >> 4;
    float acc[4][4] = {};

    for (int k0 = 0; k0 < HH; k0 += 32) {
        {
            int idx = t * 8;
            int m   = idx >> 5;
            int kk  = idx & 31;
            const float4* src = (const float4*)(Arow + (size_t)m * HH + k0 + kk);
            float4 u0 = src[0], u1 = src[1];
            As[kk + 0][m] = u0.x; As[kk + 1][m] = u0.y;
            As[kk + 2][m] = u0.z; As[kk + 3][m] = u0.w;
            As[kk + 4][m] = u1.x; As[kk + 5][m] = u1.y;
            As[kk + 6][m] = u1.z; As[kk + 7][m] = u1.w;
        }
        {
            int idx = t * 8;
            int kk  = idx >> 6;
            int nn  = idx & 63;
            const float4* src = (const float4*)(Wo + (size_t)(k0 + kk) * HH + nt * 64 + nn);
            float4* dst = (float4*)&Bs[kk][nn];
            dst[0] = src[0];
            dst[1] = src[1];
        }
        __syncthreads();
#pragma unroll
        for (int kk = 0; kk < 32; kk++) {
            float4 av = *(const float4*)&As[kk][ty * 4];
            float4 bv = *(const float4*)&Bs[kk][tx * 4];
            float a[4] = {av.x, av.y, av.z, av.w};
            float bb2[4] = {bv.x, bv.y, bv.z, bv.w};
#pragma unroll
            for (int i = 0; i < 4; i++)
#pragma unroll
                for (int j = 0; j < 4; j++)
                    acc[i][j] += a[i] * bb2[j];
        }
        __syncthreads();
    }
#pragma unroll
    for (int i = 0; i < 4; i++) {
        int r = mt * 64 + ty * 4 + i;
        float mf = (mask[r] != 0) ? 1.0f : 0.0f;
#pragma unroll
        for (int j = 0; j < 4; j++) {
            int c = nt * 64 + tx * 4 + j;
            out[(size_t)r * HH + c] = (acc[i][j] + g_xn[(size_t)r * HH + c]) * mf;
        }
    }
}

// ---------------- launch -----------------------------------------------------
extern "C" void kernel_launch(void* const* d_in, const int* in_sizes, int n_in,
                              void* d_out, int out_size) {
    const float* x     = (const float*)d_in[0];
    const int*   mask  = (const int*)  d_in[1];
    const float* Wq    = (const float*)d_in[2];
    const float* Wk    = (const float*)d_in[3];
    const float* Wv    = (const float*)d_in[4];
    const float* Wo    = (const float*)d_in[5];
    const float* gamma = (const float*)d_in[6];
    const float* beta  = (const float*)d_in[7];
    float* out = (float*)d_out;

    ln_kernel<<<BB * SS, 256>>>(x, gamma, beta);
    qkv_kernel<<<dim3(SS / 64, 3 * BB * NH), 256>>>(Wq, Wk, Wv);
    attn_kernel<<<dim3(SS / 64, BB * NH), 64>>>(mask);
    outproj_kernel<<<dim3(HH / 64, (BB * SS) / 64), 256>>>(Wo, mask, out);
}

// round 2
// speedup vs baseline: 1.4479x; 1.4479x over previous
#include <cuda_runtime.h>
#include <math.h>

#define BB 4
#define SS 2048
#define HH 512
#define NH 8
#define DKK 64
#define NEG_INF -1e30f

typedef unsigned long long ull;

// ---------------- f32x2 helpers (Blackwell packed fp32) ---------------------
__device__ __forceinline__ ull pk2(float lo, float hi) {
    ull r; asm("mov.b64 %0, {%1,%2};" : "=l"(r) : "f"(lo), "f"(hi)); return r;
}
__device__ __forceinline__ void upk2(ull v, float& lo, float& hi) {
    asm("mov.b64 {%0,%1}, %2;" : "=f"(lo), "=f"(hi) : "l"(v));
}
__device__ __forceinline__ ull fma2(ull a, ull b, ull c) {
    ull d; asm("fma.rn.f32x2 %0, %1, %2, %3;" : "=l"(d) : "l"(a), "l"(b), "l"(c)); return d;
}
__device__ __forceinline__ ull mul2(ull a, ull b) {
    ull d; asm("mul.rn.f32x2 %0, %1, %2;" : "=l"(d) : "l"(a), "l"(b)); return d;
}

// ---------------- scratch ----------------------------------------------------
__device__ float g_xn[BB * SS * HH];
__device__ float g_qc[BB * NH * SS * DKK];   // compacted q rows per (b,n)
__device__ float g_kc[BB * NH * SS * DKK];
__device__ float g_vc[BB * NH * SS * DKK];
__device__ float g_attnc[BB * SS * HH];      // compacted attention out per b
__device__ int   g_idx[BB * SS];             // valid row indices per batch
__device__ int   g_cnt[BB];                  // valid count per batch

// ---------------- 1) LayerNorm ----------------------------------------------
__global__ void ln_kernel(const float* __restrict__ x,
                          const float* __restrict__ gamma,
                          const float* __restrict__ beta) {
    int row = blockIdx.x;
    const float* xr = x + (size_t)row * HH;
    int t = threadIdx.x;
    float a = xr[t];
    float b = xr[t + 256];
    float s  = a + b;
    float sq = a * a + b * b;
    __shared__ float ssum[8], ssq[8];
    for (int o = 16; o > 0; o >>= 1) {
        s  += __shfl_xor_sync(0xffffffffu, s,  o);
        sq += __shfl_xor_sync(0xffffffffu, sq, o);
    }
    if ((t & 31) == 0) { ssum[t >> 5] = s; ssq[t >> 5] = sq; }
    __syncthreads();
    float tot = 0.f, totq = 0.f;
#pragma unroll
    for (int i = 0; i < 8; i++) { tot += ssum[i]; totq += ssq[i]; }
    float mu  = tot * (1.0f / HH);
    float var = totq * (1.0f / HH) - mu * mu;
    float inv = rsqrtf(var + 1e-5f);
    float* dst = g_xn + (size_t)row * HH;
    dst[t]       = (a - mu) * inv * gamma[t]       + beta[t];
    dst[t + 256] = (b - mu) * inv * gamma[t + 256] + beta[t + 256];
}

// ---------------- 1b) mask compaction (per batch) ----------------------------
__global__ void compact_kernel(const int* __restrict__ mask) {
    int b = blockIdx.x;
    int t = threadIdx.x;           // 256 threads, 8 elements each
    int vals[8];
    int c = 0;
#pragma unroll
    for (int i = 0; i < 8; i++) {
        vals[i] = mask[(size_t)b * SS + t * 8 + i];
        c += (vals[i] != 0);
    }
    __shared__ int s[256];
    s[t] = c;
    __syncthreads();
    for (int off = 1; off < 256; off <<= 1) {
        int v = (t >= off) ? s[t - off] : 0;
        __syncthreads();
        s[t] += v;
        __syncthreads();
    }
    int pos = s[t] - c;
#pragma unroll
    for (int i = 0; i < 8; i++) {
        if (vals[i]) g_idx[(size_t)b * SS + (pos++)] = t * 8 + i;
    }
    if (t == 255) g_cnt[b] = s[255];
}

// ---------------- 1c) zero the output ----------------------------------------
__global__ void zero_out_kernel(float* __restrict__ out) {
    int i = blockIdx.x * blockDim.x + threadIdx.x;
    ((float4*)out)[i] = make_float4(0.f, 0.f, 0.f, 0.f);
}

// ---------------- 2) QKV projection (compacted rows, f32x2) ------------------
// grid: (32 m-tiles, 96 = which*32+bn), block 128. Tile 64m x 64n, K-step 32.
__global__ __launch_bounds__(128)
void qkv_kernel(const float* __restrict__ Wq,
                const float* __restrict__ Wk,
                const float* __restrict__ Wv) {
    int mt    = blockIdx.x;
    int which = blockIdx.y >> 5;        // /32
    int bn    = blockIdx.y & 31;
    int b = bn >> 3, n = bn & 7;
    int cnt = g_cnt[b];
    if (mt * 64 >= cnt) return;

    const float* W = (which == 0 ? Wq : (which == 1 ? Wk : Wv)) + (size_t)n * HH * DKK;
    float* Cout    = (which == 0 ? g_qc : (which == 1 ? g_kc : g_vc)) + (size_t)bn * SS * DKK;

    __shared__ float As2[32][132];   // duplicated m values: As2[k][2m],[2m+1]
    __shared__ float Bs[32][64];

    int t  = threadIdx.x;
    int tx = t & 7;                  // n group (8 cols)
    int ty = t >> 3;                 // m group (4 rows)

    // per-thread A row pointer (gathered via index, clamped)
    int am  = t >> 1;                // 0..63
    int ak0 = (t & 1) * 16;          // 0 or 16
    int gm  = mt * 64 + am;
    int om  = g_idx[(size_t)b * SS + (gm < cnt ? gm : cnt - 1)];
    const float* arow = g_xn + ((size_t)b * SS + om) * HH;

    int bkk = t >> 2;                // 0..31
    int bnn = (t & 3) * 16;

    ull acc[16];
#pragma unroll
    for (int i = 0; i < 16; i++) acc[i] = 0ULL;

    for (int k0 = 0; k0 < HH; k0 += 32) {
        // A tile (64x32) -> duplicated transposed
#pragma unroll
        for (int u = 0; u < 4; u++) {
            float4 v = *(const float4*)(arow + k0 + ak0 + u * 4);
            int kk = ak0 + u * 4;
            *(float2*)&As2[kk + 0][2 * am] = make_float2(v.x, v.x);
            *(float2*)&As2[kk + 1][2 * am] = make_float2(v.y, v.y);
            *(float2*)&As2[kk + 2][2 * am] = make_float2(v.z, v.z);
            *(float2*)&As2[kk + 3][2 * am] = make_float2(v.w, v.w);
        }
        // B tile (32x64)
#pragma unroll
        for (int u = 0; u < 4; u++) {
            float4 v = *(const float4*)(W + (size_t)(k0 + bkk) * DKK + bnn + u * 4);
            *(float4*)&Bs[bkk][bnn + u * 4] = v;
        }
        __syncthreads();
#pragma unroll
        for (int kk = 0; kk < 32; kk++) {
            longlong2 a0 = *(const longlong2*)&As2[kk][ty * 8];
            longlong2 a1 = *(const longlong2*)&As2[kk][ty * 8 + 4];
            longlong2 b0 = *(const longlong2*)&Bs[kk][tx * 8];
            longlong2 b1 = *(const longlong2*)&Bs[kk][tx * 8 + 4];
            ull A0 = a0.x, A1 = a0.y, A2 = a1.x, A3 = a1.y;
            ull B0 = b0.x, B1 = b0.y, B2 = b1.x, B3 = b1.y;
            acc[0]  = fma2(A0, B0, acc[0]);  acc[1]  = fma2(A0, B1, acc[1]);
            acc[2]  = fma2(A0, B2, acc[2]);  acc[3]  = fma2(A0, B3, acc[3]);
            acc[4]  = fma2(A1, B0, acc[4]);  acc[5]  = fma2(A1, B1, acc[5]);
            acc[6]  = fma2(A1, B2, acc[6]);  acc[7]  = fma2(A1, B3, acc[7]);
            acc[8]  = fma2(A2, B0, acc[8]);  acc[9]  = fma2(A2, B1, acc[9]);
            acc[10] = fma2(A2, B2, acc[10]); acc[11] = fma2(A2, B3, acc[11]);
            acc[12] = fma2(A3, B0, acc[12]); acc[13] = fma2(A3, B1, acc[13]);
            acc[14] = fma2(A3, B2, acc[14]); acc[15] = fma2(A3, B3, acc[15]);
        }
        __syncthreads();
    }
#pragma unroll
    for (int i = 0; i < 4; i++) {
        int r = mt * 64 + ty * 4 + i;
        if (r < cnt) {
            float o[8];
            upk2(acc[i * 4 + 0], o[0], o[1]);
            upk2(acc[i * 4 + 1], o[2], o[3]);
            upk2(acc[i * 4 + 2], o[4], o[5]);
            upk2(acc[i * 4 + 3], o[6], o[7]);
            float4* dst = (float4*)(Cout + (size_t)r * DKK + tx * 8);
            dst[0] = make_float4(o[0], o[1], o[2], o[3]);
            dst[1] = make_float4(o[4], o[5], o[6], o[7]);
        }
    }
}

// ---------------- 3) flash attention over compacted keys (f32x2) -------------
// grid: (32 q-tiles, 32 bn), block 64, one query row per thread.
__global__ __launch_bounds__(64)
void attn_kernel() {
    int bn = blockIdx.y;
    int b  = bn >> 3;
    int n  = bn & 7;
    int cnt = g_cnt[b];
    if ((int)blockIdx.x * 64 >= cnt) return;
    int qi = threadIdx.x;
    int qr = blockIdx.x * 64 + qi;
    bool qvalid = (qr < cnt);
    int qrow = qvalid ? qr : cnt - 1;

    __shared__ float Ks[64 * 64];
    __shared__ float Vs[64 * 64];

    ull q2[32];
    {
        const longlong2* qp = (const longlong2*)(g_qc + ((size_t)bn * SS + qrow) * DKK);
#pragma unroll
        for (int i = 0; i < 16; i++) {
            longlong2 u = qp[i];
            q2[2 * i] = (ull)u.x; q2[2 * i + 1] = (ull)u.y;
        }
    }
    ull o2[32];
#pragma unroll
    for (int i = 0; i < 32; i++) o2[i] = 0ULL;
    float mmax = NEG_INF, l = 0.f;

    int ktiles = (cnt + 63) >> 6;
    for (int kt = 0; kt < ktiles; kt++) {
        int kbase = kt * 64;
        {
            const float4* ksrc = (const float4*)(g_kc + ((size_t)bn * SS + kbase) * DKK);
            const float4* vsrc = (const float4*)(g_vc + ((size_t)bn * SS + kbase) * DKK);
            float4* kd = (float4*)Ks;
            float4* vd = (float4*)Vs;
            float4 z = make_float4(0.f, 0.f, 0.f, 0.f);
#pragma unroll
            for (int i = 0; i < 16; i++) {
                int eidx = qi + 64 * i;
                bool ok = (kbase + (eidx >> 4)) < cnt;
                float4 kv = ksrc[eidx];
                float4 vv = vsrc[eidx];
                kd[eidx] = ok ? kv : z;
                vd[eidx] = ok ? vv : z;
            }
        }
        __syncthreads();

#pragma unroll 1
        for (int jc = 0; jc < 4; jc++) {
            float sc[16];
            float tmax = NEG_INF;
#pragma unroll
            for (int jj = 0; jj < 16; jj++) {
                int j = jc * 16 + jj;
                const longlong2* kr = (const longlong2*)(Ks + j * 64);
                ull d0 = 0ULL, d1 = 0ULL;
#pragma unroll
                for (int i = 0; i < 16; i++) {
                    longlong2 kv = kr[i];
                    d0 = fma2(q2[2 * i],     (ull)kv.x, d0);
                    d1 = fma2(q2[2 * i + 1], (ull)kv.y, d1);
                }
                float e0, e1, e2, e3;
                upk2(d0, e0, e1); upk2(d1, e2, e3);
                float dot = (e0 + e2) + (e1 + e3);
                float sval = ((kbase + j) < cnt) ? dot * 0.125f : NEG_INF;
                sc[jj] = sval;
                tmax = fmaxf(tmax, sval);
            }
            if (tmax > mmax) {
                float scale = __expf(mmax - tmax);
                l *= scale;
                ull s2 = pk2(scale, scale);
#pragma unroll
                for (int i = 0; i < 32; i++) o2[i] = mul2(o2[i], s2);
                mmax = tmax;
            }
#pragma unroll
            for (int jj = 0; jj < 16; jj++) {
                int j = jc * 16 + jj;
                float p = __expf(sc[jj] - mmax);
                l += p;
                ull p2 = pk2(p, p);
                const longlong2* vr = (const longlong2*)(Vs + j * 64);
#pragma unroll
                for (int i = 0; i < 16; i++) {
                    longlong2 vv = vr[i];
                    o2[2 * i]     = fma2(p2, (ull)vv.x, o2[2 * i]);
                    o2[2 * i + 1] = fma2(p2, (ull)vv.y, o2[2 * i + 1]);
                }
            }
        }
        __syncthreads();
    }

    if (qvalid) {
        float inv = (l > 0.f) ? (1.f / l) : 0.f;
        ull inv2 = pk2(inv, inv);
        float4* dst = (float4*)(g_attnc + ((size_t)b * SS + qrow) * HH + n * DKK);
#pragma unroll
        for (int i = 0; i < 16; i++) {
            float4 w;
            upk2(mul2(o2[2 * i], inv2),     w.x, w.y);
            upk2(mul2(o2[2 * i + 1], inv2), w.z, w.w);
            dst[i] = w;
        }
    }
}

// ---------------- 4) out projection + residual + scatter (f32x2) -------------
// grid: (8 n-tiles, 128 = b*32 + mt), block 128. Tile 64m x 64n, K=512.
__global__ __launch_bounds__(128)
void outproj_kernel(const float* __restrict__ Wo,
                    float* __restrict__ out) {
    int nt = blockIdx.x;
    int b  = blockIdx.y >> 5;
    int mt = blockIdx.y & 31;
    int cnt = g_cnt[b];
    if (mt * 64 >= cnt) return;

    __shared__ float As2[32][132];
    __shared__ float Bs[32][64];

    int t  = threadIdx.x;
    int tx = t & 7;
    int ty = t >> 3;

    int am  = t >> 1;
    int ak0 = (t & 1) * 16;
    const float* arow = g_attnc + ((size_t)b * SS + mt * 64 + am) * HH;

    int bkk = t >> 2;
    int bnn = (t & 3) * 16;

    ull acc[16];
#pragma unroll
    for (int i = 0; i < 16; i++) acc[i] = 0ULL;

    for (int k0 = 0; k0 < HH; k0 += 32) {
#pragma unroll
        for (int u = 0; u < 4; u++) {
            float4 v = *(const float4*)(arow + k0 + ak0 + u * 4);
            int kk = ak0 + u * 4;
            *(float2*)&As2[kk + 0][2 * am] = make_float2(v.x, v.x);
            *(float2*)&As2[kk + 1][2 * am] = make_float2(v.y, v.y);
            *(float2*)&As2[kk + 2][2 * am] = make_float2(v.z, v.z);
            *(float2*)&As2[kk + 3][2 * am] = make_float2(v.w, v.w);
        }
#pragma unroll
        for (int u = 0; u < 4; u++) {
            float4 v = *(const float4*)(Wo + (size_t)(k0 + bkk) * HH + nt * 64 + bnn + u * 4);
            *(float4*)&Bs[bkk][bnn + u * 4] = v;
        }
        __syncthreads();
#pragma unroll
        for (int kk = 0; kk < 32; kk++) {
            longlong2 a0 = *(const longlong2*)&As2[kk][ty * 8];
            longlong2 a1 = *(const longlong2*)&As2[kk][ty * 8 + 4];
            longlong2 b0 = *(const longlong2*)&Bs[kk][tx * 8];
            longlong2 b1 = *(const longlong2*)&Bs[kk][tx * 8 + 4];
            ull A0 = a0.x, A1 = a0.y, A2 = a1.x, A3 = a1.y;
            ull B0 = b0.x, B1 = b0.y, B2 = b1.x, B3 = b1.y;
            acc[0]  = fma2(A0, B0, acc[0]);  acc[1]  = fma2(A0, B1, acc[1]);
            acc[2]  = fma2(A0, B2, acc[2]);  acc[3]  = fma2(A0, B3, acc[3]);
            acc[4]  = fma2(A1, B0, acc[4]);  acc[5]  = fma2(A1, B1, acc[5]);
            acc[6]  = fma2(A1, B2, acc[6]);  acc[7]  = fma2(A1, B3, acc[7]);
            acc[8]  = fma2(A2, B0, acc[8]);  acc[9]  = fma2(A2, B1, acc[9]);
            acc[10] = fma2(A2, B2, acc[10]); acc[11] = fma2(A2, B3, acc[11]);
            acc[12] = fma2(A3, B0, acc[12]); acc[13] = fma2(A3, B1, acc[13]);
            acc[14] = fma2(A3, B2, acc[14]); acc[15] = fma2(A3, B3, acc[15]);
        }
        __syncthreads();
    }
#pragma unroll
    for (int i = 0; i < 4; i++) {
        int r = mt * 64 + ty * 4 + i;
        if (r < cnt) {
            int orig = g_idx[(size_t)b * SS + r];
            size_t rowoff = ((size_t)b * SS + orig) * HH + nt * 64 + tx * 8;
            float o[8];
            upk2(acc[i * 4 + 0], o[0], o[1]);
            upk2(acc[i * 4 + 1], o[2], o[3]);
            upk2(acc[i * 4 + 2], o[4], o[5]);
            upk2(acc[i * 4 + 3], o[6], o[7]);
            float4 x0 = *(const float4*)(g_xn + rowoff);
            float4 x1 = *(const float4*)(g_xn + rowoff + 4);
            *(float4*)(out + rowoff)     = make_float4(o[0] + x0.x, o[1] + x0.y, o[2] + x0.z, o[3] + x0.w);
            *(float4*)(out + rowoff + 4) = make_float4(o[4] + x1.x, o[5] + x1.y, o[6] + x1.z, o[7] + x1.w);
        }
    }
}

// ---------------- launch ------------------------------------------------------
extern "C" void kernel_launch(void* const* d_in, const int* in_sizes, int n_in,
                              void* d_out, int out_size) {
    const float* x     = (const float*)d_in[0];
    const int*   mask  = (const int*)  d_in[1];
    const float* Wq    = (const float*)d_in[2];
    const float* Wk    = (const float*)d_in[3];
    const float* Wv    = (const float*)d_in[4];
    const float* Wo    = (const float*)d_in[5];
    const float* gamma = (const float*)d_in[6];
    const float* beta  = (const float*)d_in[7];
    float* out = (float*)d_out;

    zero_out_kernel<<<(BB * SS * HH) / (256 * 4), 256>>>(out);
    ln_kernel<<<BB * SS, 256>>>(x, gamma, beta);
    compact_kernel<<<BB, 256>>>(mask);
    qkv_kernel<<<dim3(SS / 64, 96), 128>>>(Wq, Wk, Wv);
    attn_kernel<<<dim3(SS / 64, BB * NH), 64>>>();
    outproj_kernel<<<dim3(HH / 64, BB * (SS / 64)), 128>>>(Wo, out);
}

// round 4
// speedup vs baseline: 1.9254x; 1.3298x over previous
#include <cuda_runtime.h>
#include <math.h>

#define BB 4
#define SS 2048
#define HH 512
#define NH 8
#define DKK 64
#define NEG_INF -1e30f

typedef unsigned long long ull;

// ---------------- f32x2 helpers (Blackwell packed fp32) ---------------------
__device__ __forceinline__ ull pk2(float lo, float hi) {
    ull r; asm("mov.b64 %0, {%1,%2};" : "=l"(r) : "f"(lo), "f"(hi)); return r;
}
__device__ __forceinline__ void upk2(ull v, float& lo, float& hi) {
    asm("mov.b64 {%0,%1}, %2;" : "=f"(lo), "=f"(hi) : "l"(v));
}
__device__ __forceinline__ ull fma2(ull a, ull b, ull c) {
    ull d; asm("fma.rn.f32x2 %0, %1, %2, %3;" : "=l"(d) : "l"(a), "l"(b), "l"(c)); return d;
}
__device__ __forceinline__ ull mul2(ull a, ull b) {
    ull d; asm("mul.rn.f32x2 %0, %1, %2;" : "=l"(d) : "l"(a), "l"(b)); return d;
}
__device__ __forceinline__ ull add2(ull a, ull b) {
    ull d; asm("add.rn.f32x2 %0, %1, %2;" : "=l"(d) : "l"(a), "l"(b)); return d;
}

// ---------------- scratch ----------------------------------------------------
__device__ float g_xn[BB * SS * HH];
__device__ float g_qc[BB * NH * SS * DKK];
__device__ float g_kc[BB * NH * SS * DKK];
__device__ float g_vc[BB * NH * SS * DKK];
__device__ float g_attnc[BB * SS * HH];
__device__ int   g_idx[BB * SS];
__device__ int   g_cnt[BB];

// ---------------- 1) LayerNorm ----------------------------------------------
__global__ void ln_kernel(const float* __restrict__ x,
                          const float* __restrict__ gamma,
                          const float* __restrict__ beta) {
    int row = blockIdx.x;
    const float* xr = x + (size_t)row * HH;
    int t = threadIdx.x;
    float a = xr[t];
    float b = xr[t + 256];
    float s  = a + b;
    float sq = a * a + b * b;
    __shared__ float ssum[8], ssq[8];
    for (int o = 16; o > 0; o >>= 1) {
        s  += __shfl_xor_sync(0xffffffffu, s,  o);
        sq += __shfl_xor_sync(0xffffffffu, sq, o);
    }
    if ((t & 31) == 0) { ssum[t >> 5] = s; ssq[t >> 5] = sq; }
    __syncthreads();
    float tot = 0.f, totq = 0.f;
#pragma unroll
    for (int i = 0; i < 8; i++) { tot += ssum[i]; totq += ssq[i]; }
    float mu  = tot * (1.0f / HH);
    float var = totq * (1.0f / HH) - mu * mu;
    float inv = rsqrtf(var + 1e-5f);
    float* dst = g_xn + (size_t)row * HH;
    dst[t]       = (a - mu) * inv * gamma[t]       + beta[t];
    dst[t + 256] = (b - mu) * inv * gamma[t + 256] + beta[t + 256];
}

// ---------------- 1b) mask compaction ----------------------------------------
__global__ void compact_kernel(const int* __restrict__ mask) {
    int b = blockIdx.x;
    int t = threadIdx.x;
    int vals[8];
    int c = 0;
#pragma unroll
    for (int i = 0; i < 8; i++) {
        vals[i] = mask[(size_t)b * SS + t * 8 + i];
        c += (vals[i] != 0);
    }
    __shared__ int s[256];
    s[t] = c;
    __syncthreads();
    for (int off = 1; off < 256; off <<= 1) {
        int v = (t >= off) ? s[t - off] : 0;
        __syncthreads();
        s[t] += v;
        __syncthreads();
    }
    int pos = s[t] - c;
#pragma unroll
    for (int i = 0; i < 8; i++) {
        if (vals[i]) g_idx[(size_t)b * SS + (pos++)] = t * 8 + i;
    }
    if (t == 255) g_cnt[b] = s[255];
}

// ---------------- 1c) zero output ---------------------------------------------
__global__ void zero_out_kernel(float* __restrict__ out) {
    int i = blockIdx.x * blockDim.x + threadIdx.x;
    ((float4*)out)[i] = make_float4(0.f, 0.f, 0.f, 0.f);
}

// ---------------- 2) QKV projection: 128m x 64n tile, 8x8 micro, f32x2 -------
// grid: (16 m-tiles, 96 = which*32 + bn), block 128
__global__ __launch_bounds__(128)
void qkv_kernel(const float* __restrict__ Wq,
                const float* __restrict__ Wk,
                const float* __restrict__ Wv) {
    int mt    = blockIdx.x;
    int which = blockIdx.y >> 5;
    int bn    = blockIdx.y & 31;
    int b = bn >> 3, n = bn & 7;
    int cnt = g_cnt[b];
    if (mt * 128 >= cnt) return;

    const float* W = (which == 0 ? Wq : (which == 1 ? Wk : Wv)) + (size_t)n * HH * DKK;
    float* Cout    = (which == 0 ? g_qc : (which == 1 ? g_kc : g_vc)) + (size_t)bn * SS * DKK;

    __shared__ __align__(16) float As[16][132];   // transposed A: [k][m]
    __shared__ __align__(16) float Bs[16][64];    // [k][n]

    int t  = threadIdx.x;
    int tx = t & 7;          // n group
    int ty = t >> 3;         // m group (0..15)

    int gm = mt * 128 + t;
    int om = g_idx[(size_t)b * SS + (gm < cnt ? gm : cnt - 1)];
    const float* arow = g_xn + ((size_t)b * SS + om) * HH;
    int kk_b = t >> 3;
    int nn_b = (t & 7) * 8;

    ull acc[32];
#pragma unroll
    for (int i = 0; i < 32; i++) acc[i] = 0ULL;

    float4 a_r[4], b_r[2];
#pragma unroll
    for (int u = 0; u < 4; u++) a_r[u] = *(const float4*)(arow + u * 4);
    b_r[0] = *(const float4*)(W + (size_t)kk_b * DKK + nn_b);
    b_r[1] = *(const float4*)(W + (size_t)kk_b * DKK + nn_b + 4);

    for (int k0 = 0; k0 < HH; k0 += 16) {
        __syncthreads();
#pragma unroll
        for (int u = 0; u < 4; u++) {
            As[u * 4 + 0][t] = a_r[u].x;
            As[u * 4 + 1][t] = a_r[u].y;
            As[u * 4 + 2][t] = a_r[u].z;
            As[u * 4 + 3][t] = a_r[u].w;
        }
        *(float4*)&Bs[kk_b][nn_b]     = b_r[0];
        *(float4*)&Bs[kk_b][nn_b + 4] = b_r[1];
        __syncthreads();
        if (k0 + 16 < HH) {
#pragma unroll
            for (int u = 0; u < 4; u++) a_r[u] = *(const float4*)(arow + k0 + 16 + u * 4);
            b_r[0] = *(const float4*)(W + (size_t)(k0 + 16 + kk_b) * DKK + nn_b);
            b_r[1] = *(const float4*)(W + (size_t)(k0 + 16 + kk_b) * DKK + nn_b + 4);
        }
#pragma unroll
        for (int kk = 0; kk < 16; kk++) {
            float4 av0 = *(const float4*)&As[kk][ty * 8];
            float4 av1 = *(const float4*)&As[kk][ty * 8 + 4];
            longlong2 bb0 = *(const longlong2*)&Bs[kk][tx * 4];
            longlong2 bb1 = *(const longlong2*)&Bs[kk][32 + tx * 4];
            ull B0 = (ull)bb0.x, B1 = (ull)bb0.y, B2 = (ull)bb1.x, B3 = (ull)bb1.y;
            float am[8] = {av0.x, av0.y, av0.z, av0.w, av1.x, av1.y, av1.z, av1.w};
#pragma unroll
            for (int m = 0; m < 8; m++) {
                ull Am = pk2(am[m], am[m]);
                acc[m * 4 + 0] = fma2(Am, B0, acc[m * 4 + 0]);
                acc[m * 4 + 1] = fma2(Am, B1, acc[m * 4 + 1]);
                acc[m * 4 + 2] = fma2(Am, B2, acc[m * 4 + 2]);
                acc[m * 4 + 3] = fma2(Am, B3, acc[m * 4 + 3]);
            }
        }
    }
#pragma unroll
    for (int i = 0; i < 8; i++) {
        int r = mt * 128 + ty * 8 + i;
        if (r < cnt) {
            float o[8];
            upk2(acc[i * 4 + 0], o[0], o[1]);
            upk2(acc[i * 4 + 1], o[2], o[3]);
            upk2(acc[i * 4 + 2], o[4], o[5]);
            upk2(acc[i * 4 + 3], o[6], o[7]);
            float* dst = Cout + (size_t)r * DKK;
            *(float4*)(dst + tx * 4)      = make_float4(o[0], o[1], o[2], o[3]);
            *(float4*)(dst + 32 + tx * 4) = make_float4(o[4], o[5], o[6], o[7]);
        }
    }
}

// ---------------- 3) flash attention, split-d x2, f32x2 -----------------------
// grid: (16 q-tiles of 128, 32 bn), block 256 (2 threads per q row)
__global__ __launch_bounds__(256)
void attn_kernel() {
    int bn = blockIdx.y;
    int b  = bn >> 3;
    int n  = bn & 7;
    int cnt = g_cnt[b];
    if ((int)blockIdx.x * 128 >= cnt) return;
    int t = threadIdx.x;
    int qi = t >> 1;
    int half = t & 1;
    int qr = blockIdx.x * 128 + qi;
    bool qvalid = (qr < cnt);
    int qrow = qvalid ? qr : cnt - 1;

    __shared__ __align__(16) float Ks[64 * 64];
    __shared__ __align__(16) float Vs[64 * 64];

    ull q2[16];
    {
        const longlong2* qp = (const longlong2*)(g_qc + ((size_t)bn * SS + qrow) * DKK + half * 32);
#pragma unroll
        for (int i = 0; i < 8; i++) {
            longlong2 u = qp[i];
            q2[2 * i] = (ull)u.x; q2[2 * i + 1] = (ull)u.y;
        }
    }
    ull o2[16];
#pragma unroll
    for (int i = 0; i < 16; i++) o2[i] = 0ULL;
    float mmax = NEG_INF, l = 0.f;

    int ktiles = (cnt + 63) >> 6;
    for (int kt = 0; kt < ktiles; kt++) {
        int kbase = kt * 64;
        {
            const float4* ksrc = (const float4*)(g_kc + ((size_t)bn * SS + kbase) * DKK);
            const float4* vsrc = (const float4*)(g_vc + ((size_t)bn * SS + kbase) * DKK);
            float4* kd = (float4*)Ks;
            float4* vd = (float4*)Vs;
            float4 z = make_float4(0.f, 0.f, 0.f, 0.f);
#pragma unroll
            for (int i = 0; i < 4; i++) {
                int eidx = t + 256 * i;
                bool ok = (kbase + (eidx >> 4)) < cnt;
                float4 kv = ksrc[eidx];
                float4 vv = vsrc[eidx];
                kd[eidx] = ok ? kv : z;
                vd[eidx] = ok ? vv : z;
            }
        }
        __syncthreads();

#pragma unroll 1
        for (int jc = 0; jc < 4; jc++) {
            float sc[16];
            float tmax = NEG_INF;
#pragma unroll
            for (int jj = 0; jj < 16; jj++) {
                int j = jc * 16 + jj;
                const longlong2* kr = (const longlong2*)(Ks + j * 64 + half * 32);
                ull d0 = 0ULL, d1 = 0ULL, d2 = 0ULL, d3 = 0ULL;
#pragma unroll
                for (int i = 0; i < 4; i++) {
                    longlong2 k0 = kr[2 * i];
                    longlong2 k1 = kr[2 * i + 1];
                    d0 = fma2(q2[4 * i + 0], (ull)k0.x, d0);
                    d1 = fma2(q2[4 * i + 1], (ull)k0.y, d1);
                    d2 = fma2(q2[4 * i + 2], (ull)k1.x, d2);
                    d3 = fma2(q2[4 * i + 3], (ull)k1.y, d3);
                }
                ull s = add2(add2(d0, d1), add2(d2, d3));
                float lo, hi;
                upk2(s, lo, hi);
                float dh = lo + hi;
                float dot = dh + __shfl_xor_sync(0xffffffffu, dh, 1);
                float sval = ((kbase + j) < cnt) ? dot * 0.125f : NEG_INF;
                sc[jj] = sval;
                tmax = fmaxf(tmax, sval);
            }
            if (tmax > mmax) {
                float scale = __expf(mmax - tmax);
                l *= scale;
                ull s2 = pk2(scale, scale);
#pragma unroll
                for (int i = 0; i < 16; i++) o2[i] = mul2(o2[i], s2);
                mmax = tmax;
            }
#pragma unroll
            for (int jj = 0; jj < 16; jj++) {
                int j = jc * 16 + jj;
                float p = __expf(sc[jj] - mmax);
                l += p;
                ull p2 = pk2(p, p);
                const longlong2* vr = (const longlong2*)(Vs + j * 64 + half * 32);
#pragma unroll
                for (int i = 0; i < 8; i++) {
                    longlong2 vv = vr[i];
                    o2[2 * i]     = fma2(p2, (ull)vv.x, o2[2 * i]);
                    o2[2 * i + 1] = fma2(p2, (ull)vv.y, o2[2 * i + 1]);
                }
            }
        }
        __syncthreads();
    }

    if (qvalid) {
        float inv = (l > 0.f) ? (1.f / l) : 0.f;
        ull inv2 = pk2(inv, inv);
        float4* dst = (float4*)(g_attnc + ((size_t)b * SS + qrow) * HH + n * DKK + half * 32);
#pragma unroll
        for (int i = 0; i < 8; i++) {
            float4 w;
            upk2(mul2(o2[2 * i], inv2),     w.x, w.y);
            upk2(mul2(o2[2 * i + 1], inv2), w.z, w.w);
            dst[i] = w;
        }
    }
}

// ---------------- 4) out projection: 128m x 64n tile, 8x8 micro ---------------
// grid: (8 n-tiles, 64 = b*16 + mt), block 128
__global__ __launch_bounds__(128)
void outproj_kernel(const float* __restrict__ Wo,
                    float* __restrict__ out) {
    int nt = blockIdx.x;
    int b  = blockIdx.y >> 4;
    int mt = blockIdx.y & 15;
    int cnt = g_cnt[b];
    if (mt * 128 >= cnt) return;

    __shared__ __align__(16) float As[16][132];
    __shared__ __align__(16) float Bs[16][64];

    int t  = threadIdx.x;
    int tx = t & 7;
    int ty = t >> 3;

    const float* arow = g_attnc + ((size_t)b * SS + mt * 128 + t) * HH;
    int kk_b = t >> 3;
    int nn_b = (t & 7) * 8;

    ull acc[32];
#pragma unroll
    for (int i = 0; i < 32; i++) acc[i] = 0ULL;

    float4 a_r[4], b_r[2];
#pragma unroll
    for (int u = 0; u < 4; u++) a_r[u] = *(const float4*)(arow + u * 4);
    b_r[0] = *(const float4*)(Wo + (size_t)kk_b * HH + nt * 64 + nn_b);
    b_r[1] = *(const float4*)(Wo + (size_t)kk_b * HH + nt * 64 + nn_b + 4);

    for (int k0 = 0; k0 < HH; k0 += 16) {
        __syncthreads();
#pragma unroll
        for (int u = 0; u < 4; u++) {
            As[u * 4 + 0][t] = a_r[u].x;
            As[u * 4 + 1][t] = a_r[u].y;
            As[u * 4 + 2][t] = a_r[u].z;
            As[u * 4 + 3][t] = a_r[u].w;
        }
        *(float4*)&Bs[kk_b][nn_b]     = b_r[0];
        *(float4*)&Bs[kk_b][nn_b + 4] = b_r[1];
        __syncthreads();
        if (k0 + 16 < HH) {
#pragma unroll
            for (int u = 0; u < 4; u++) a_r[u] = *(const float4*)(arow + k0 + 16 + u * 4);
            b_r[0] = *(const float4*)(Wo + (size_t)(k0 + 16 + kk_b) * HH + nt * 64 + nn_b);
            b_r[1] = *(const float4*)(Wo + (size_t)(k0 + 16 + kk_b) * HH + nt * 64 + nn_b + 4);
        }
#pragma unroll
        for (int kk = 0; kk < 16; kk++) {
            float4 av0 = *(const float4*)&As[kk][ty * 8];
            float4 av1 = *(const float4*)&As[kk][ty * 8 + 4];
            longlong2 bb0 = *(const longlong2*)&Bs[kk][tx * 4];
            longlong2 bb1 = *(const longlong2*)&Bs[kk][32 + tx * 4];
            ull B0 = (ull)bb0.x, B1 = (ull)bb0.y, B2 = (ull)bb1.x, B3 = (ull)bb1.y;
            float am[8] = {av0.x, av0.y, av0.z, av0.w, av1.x, av1.y, av1.z, av1.w};
#pragma unroll
            for (int m = 0; m < 8; m++) {
                ull Am = pk2(am[m], am[m]);
                acc[m * 4 + 0] = fma2(Am, B0, acc[m * 4 + 0]);
                acc[m * 4 + 1] = fma2(Am, B1, acc[m * 4 + 1]);
                acc[m * 4 + 2] = fma2(Am, B2, acc[m * 4 + 2]);
                acc[m * 4 + 3] = fma2(Am, B3, acc[m * 4 + 3]);
            }
        }
    }
#pragma unroll
    for (int i = 0; i < 8; i++) {
        int r = mt * 128 + ty * 8 + i;
        if (r < cnt) {
            float o[8];
            upk2(acc[i * 4 + 0], o[0], o[1]);
            upk2(acc[i * 4 + 1], o[2], o[3]);
            upk2(acc[i * 4 + 2], o[4], o[5]);
            upk2(acc[i * 4 + 3], o[6], o[7]);
            int orig = g_idx[(size_t)b * SS + r];
            size_t rowoff = ((size_t)b * SS + orig) * HH + nt * 64;
            float4 x0 = *(const float4*)(g_xn + rowoff + tx * 4);
            float4 x1 = *(const float4*)(g_xn + rowoff + 32 + tx * 4);
            *(float4*)(out + rowoff + tx * 4) =
                make_float4(o[0] + x0.x, o[1] + x0.y, o[2] + x0.z, o[3] + x0.w);
            *(float4*)(out + rowoff + 32 + tx * 4) =
                make_float4(o[4] + x1.x, o[5] + x1.y, o[6] + x1.z, o[7] + x1.w);
        }
    }
}

// ---------------- launch ------------------------------------------------------
extern "C" void kernel_launch(void* const* d_in, const int* in_sizes, int n_in,
                              void* d_out, int out_size) {
    const float* x     = (const float*)d_in[0];
    const int*   mask  = (const int*)  d_in[1];
    const float* Wq    = (const float*)d_in[2];
    const float* Wk    = (const float*)d_in[3];
    const float* Wv    = (const float*)d_in[4];
    const float* Wo    = (const float*)d_in[5];
    const float* gamma = (const float*)d_in[6];
    const float* beta  = (const float*)d_in[7];
    float* out = (float*)d_out;

    zero_out_kernel<<<(BB * SS * HH) / (256 * 4), 256>>>(out);
    ln_kernel<<<BB * SS, 256>>>(x, gamma, beta);
    compact_kernel<<<BB, 256>>>(mask);
    qkv_kernel<<<dim3(SS / 128, 96), 128>>>(Wq, Wk, Wv);
    attn_kernel<<<dim3(SS / 128, BB * NH), 256>>>();
    outproj_kernel<<<dim3(HH / 64, BB * (SS / 128)), 128>>>(Wo, out);
}

// round 5
// speedup vs baseline: 2.2241x; 1.1551x over previous
#include <cuda_runtime.h>
#include <math.h>

#define BB 4
#define SS 2048
#define HH 512
#define NH 8
#define DKK 64

typedef unsigned long long ull;

// ---------------- f32x2 helpers (Blackwell packed fp32) ---------------------
__device__ __forceinline__ ull pk2(float lo, float hi) {
    ull r; asm("mov.b64 %0, {%1,%2};" : "=l"(r) : "f"(lo), "f"(hi)); return r;
}
__device__ __forceinline__ void upk2(ull v, float& lo, float& hi) {
    asm("mov.b64 {%0,%1}, %2;" : "=f"(lo), "=f"(hi) : "l"(v));
}
__device__ __forceinline__ ull fma2(ull a, ull b, ull c) {
    ull d; asm("fma.rn.f32x2 %0, %1, %2, %3;" : "=l"(d) : "l"(a), "l"(b), "l"(c)); return d;
}
__device__ __forceinline__ ull mul2(ull a, ull b) {
    ull d; asm("mul.rn.f32x2 %0, %1, %2;" : "=l"(d) : "l"(a), "l"(b)); return d;
}

// ---------------- scratch ----------------------------------------------------
__device__ float g_xn[BB * SS * HH];
__device__ float g_qc[BB * NH * SS * DKK];
__device__ float g_kc[BB * NH * SS * DKK];
__device__ float g_vc[BB * NH * SS * DKK];
__device__ float g_attnc[BB * SS * HH];
__device__ int   g_idx[BB * SS];
__device__ int   g_cnt[BB];

// ---------------- 1) LayerNorm ----------------------------------------------
__global__ void ln_kernel(const float* __restrict__ x,
                          const float* __restrict__ gamma,
                          const float* __restrict__ beta) {
    int row = blockIdx.x;
    const float* xr = x + (size_t)row * HH;
    int t = threadIdx.x;
    float a = xr[t];
    float b = xr[t + 256];
    float s  = a + b;
    float sq = a * a + b * b;
    __shared__ float ssum[8], ssq[8];
    for (int o = 16; o > 0; o >>= 1) {
        s  += __shfl_xor_sync(0xffffffffu, s,  o);
        sq += __shfl_xor_sync(0xffffffffu, sq, o);
    }
    if ((t & 31) == 0) { ssum[t >> 5] = s; ssq[t >> 5] = sq; }
    __syncthreads();
    float tot = 0.f, totq = 0.f;
#pragma unroll
    for (int i = 0; i < 8; i++) { tot += ssum[i]; totq += ssq[i]; }
    float mu  = tot * (1.0f / HH);
    float var = totq * (1.0f / HH) - mu * mu;
    float inv = rsqrtf(var + 1e-5f);
    float* dst = g_xn + (size_t)row * HH;
    dst[t]       = (a - mu) * inv * gamma[t]       + beta[t];
    dst[t + 256] = (b - mu) * inv * gamma[t + 256] + beta[t + 256];
}

// ---------------- 1b) mask compaction ----------------------------------------
__global__ void compact_kernel(const int* __restrict__ mask) {
    int b = blockIdx.x;
    int t = threadIdx.x;
    int vals[8];
    int c = 0;
#pragma unroll
    for (int i = 0; i < 8; i++) {
        vals[i] = mask[(size_t)b * SS + t * 8 + i];
        c += (vals[i] != 0);
    }
    __shared__ int s[256];
    s[t] = c;
    __syncthreads();
    for (int off = 1; off < 256; off <<= 1) {
        int v = (t >= off) ? s[t - off] : 0;
        __syncthreads();
        s[t] += v;
        __syncthreads();
    }
    int pos = s[t] - c;
#pragma unroll
    for (int i = 0; i < 8; i++) {
        if (vals[i]) g_idx[(size_t)b * SS + (pos++)] = t * 8 + i;
    }
    if (t == 255) g_cnt[b] = s[255];
}

// ---------------- 1c) zero output ---------------------------------------------
__global__ void zero_out_kernel(float* __restrict__ out) {
    int i = blockIdx.x * blockDim.x + threadIdx.x;
    ((float4*)out)[i] = make_float4(0.f, 0.f, 0.f, 0.f);
}

// ---------------- 2) QKV projection: 128m x 64n tile, 8x8 micro, f32x2 -------
__global__ __launch_bounds__(128)
void qkv_kernel(const float* __restrict__ Wq,
                const float* __restrict__ Wk,
                const float* __restrict__ Wv) {
    int mt    = blockIdx.x;
    int which = blockIdx.y >> 5;
    int bn    = blockIdx.y & 31;
    int b = bn >> 3, n = bn & 7;
    int cnt = g_cnt[b];
    if (mt * 128 >= cnt) return;

    const float* W = (which == 0 ? Wq : (which == 1 ? Wk : Wv)) + (size_t)n * HH * DKK;
    float* Cout    = (which == 0 ? g_qc : (which == 1 ? g_kc : g_vc)) + (size_t)bn * SS * DKK;

    __shared__ __align__(16) float As[16][132];
    __shared__ __align__(16) float Bs[16][64];

    int t  = threadIdx.x;
    int tx = t & 7;
    int ty = t >> 3;

    int gm = mt * 128 + t;
    int om = g_idx[(size_t)b * SS + (gm < cnt ? gm : cnt - 1)];
    const float* arow = g_xn + ((size_t)b * SS + om) * HH;
    int kk_b = t >> 3;
    int nn_b = (t & 7) * 8;

    ull acc[32];
#pragma unroll
    for (int i = 0; i < 32; i++) acc[i] = 0ULL;

    float4 a_r[4], b_r[2];
#pragma unroll
    for (int u = 0; u < 4; u++) a_r[u] = *(const float4*)(arow + u * 4);
    b_r[0] = *(const float4*)(W + (size_t)kk_b * DKK + nn_b);
    b_r[1] = *(const float4*)(W + (size_t)kk_b * DKK + nn_b + 4);

    for (int k0 = 0; k0 < HH; k0 += 16) {
        __syncthreads();
#pragma unroll
        for (int u = 0; u < 4; u++) {
            As[u * 4 + 0][t] = a_r[u].x;
            As[u * 4 + 1][t] = a_r[u].y;
            As[u * 4 + 2][t] = a_r[u].z;
            As[u * 4 + 3][t] = a_r[u].w;
        }
        *(float4*)&Bs[kk_b][nn_b]     = b_r[0];
        *(float4*)&Bs[kk_b][nn_b + 4] = b_r[1];
        __syncthreads();
        if (k0 + 16 < HH) {
#pragma unroll
            for (int u = 0; u < 4; u++) a_r[u] = *(const float4*)(arow + k0 + 16 + u * 4);
            b_r[0] = *(const float4*)(W + (size_t)(k0 + 16 + kk_b) * DKK + nn_b);
            b_r[1] = *(const float4*)(W + (size_t)(k0 + 16 + kk_b) * DKK + nn_b + 4);
        }
#pragma unroll
        for (int kk = 0; kk < 16; kk++) {
            float4 av0 = *(const float4*)&As[kk][ty * 8];
            float4 av1 = *(const float4*)&As[kk][ty * 8 + 4];
            longlong2 bb0 = *(const longlong2*)&Bs[kk][tx * 4];
            longlong2 bb1 = *(const longlong2*)&Bs[kk][32 + tx * 4];
            ull B0 = (ull)bb0.x, B1 = (ull)bb0.y, B2 = (ull)bb1.x, B3 = (ull)bb1.y;
            float am[8] = {av0.x, av0.y, av0.z, av0.w, av1.x, av1.y, av1.z, av1.w};
#pragma unroll
            for (int m = 0; m < 8; m++) {
                ull Am = pk2(am[m], am[m]);
                acc[m * 4 + 0] = fma2(Am, B0, acc[m * 4 + 0]);
                acc[m * 4 + 1] = fma2(Am, B1, acc[m * 4 + 1]);
                acc[m * 4 + 2] = fma2(Am, B2, acc[m * 4 + 2]);
                acc[m * 4 + 3] = fma2(Am, B3, acc[m * 4 + 3]);
            }
        }
    }
#pragma unroll
    for (int i = 0; i < 8; i++) {
        int r = mt * 128 + ty * 8 + i;
        if (r < cnt) {
            float o[8];
            upk2(acc[i * 4 + 0], o[0], o[1]);
            upk2(acc[i * 4 + 1], o[2], o[3]);
            upk2(acc[i * 4 + 2], o[4], o[5]);
            upk2(acc[i * 4 + 3], o[6], o[7]);
            float* dst = Cout + (size_t)r * DKK;
            *(float4*)(dst + tx * 4)      = make_float4(o[0], o[1], o[2], o[3]);
            *(float4*)(dst + 32 + tx * 4) = make_float4(o[4], o[5], o[6], o[7]);
        }
    }
}

// ---------------- 3) attention: tiled GEMM-GEMM, no-max softmax --------------
// grid: (32 q-tiles of 64, 32 bn), block 128.
// Thread (tx=t&7, ty=t>>3) owns 4 q rows (ty*4..+3) and 8 k cols / 8 d cols.
__global__ __launch_bounds__(128)
void attn_kernel() {
    int bn = blockIdx.y;
    int b  = bn >> 3;
    int n  = bn & 7;
    int cnt = g_cnt[b];
    int qbase = blockIdx.x * 64;
    if (qbase >= cnt) return;

    int t  = threadIdx.x;
    int tx = t & 7;
    int ty = t >> 3;

    __shared__ __align__(16) float Qs[64][64];    // [d][q]
    __shared__ __align__(16) float KPs[64][64];   // [d][k] then reused as P [k][q]
    __shared__ __align__(16) float Vs[64][64];    // [k][d]

    // load Q tile transposed (rows >= cnt read zeros from never-written g_qc)
    {
        int qi = t >> 1;
        int dh = (t & 1) * 32;
        const float4* src = (const float4*)(g_qc + ((size_t)bn * SS + qbase + qi) * DKK + dh);
#pragma unroll
        for (int u = 0; u < 8; u++) {
            float4 v = src[u];
            int d = dh + u * 4;
            Qs[d + 0][qi] = v.x; Qs[d + 1][qi] = v.y;
            Qs[d + 2][qi] = v.z; Qs[d + 3][qi] = v.w;
        }
    }

    ull o2[16];
#pragma unroll
    for (int i = 0; i < 16; i++) o2[i] = 0ULL;
    float l[4] = {0.f, 0.f, 0.f, 0.f};

    int ktiles = (cnt + 63) >> 6;
    for (int kt = 0; kt < ktiles; kt++) {
        int kbase = kt * 64;
        __syncthreads();   // previous GEMM2 done with KPs(P) and Vs
        // load K transposed + V natural (rows >= cnt are zeros)
        {
            int ki = t >> 1;
            int dh = (t & 1) * 32;
            const float4* ksrc = (const float4*)(g_kc + ((size_t)bn * SS + kbase + ki) * DKK + dh);
            const float4* vsrc = (const float4*)(g_vc + ((size_t)bn * SS + kbase + ki) * DKK + dh);
            float4* vdst = (float4*)&Vs[ki][dh];
#pragma unroll
            for (int u = 0; u < 8; u++) {
                float4 kv = ksrc[u];
                int d = dh + u * 4;
                KPs[d + 0][ki] = kv.x; KPs[d + 1][ki] = kv.y;
                KPs[d + 2][ki] = kv.z; KPs[d + 3][ki] = kv.w;
                vdst[u] = vsrc[u];
            }
        }
        __syncthreads();

        // GEMM1: S[4q][8k] = sum_d Q[d][q] * K[d][k]
        ull s2[16];
#pragma unroll
        for (int i = 0; i < 16; i++) s2[i] = 0ULL;
#pragma unroll 4
        for (int dd = 0; dd < 64; dd++) {
            float4 qv = *(const float4*)&Qs[dd][ty * 4];
            longlong2 kb0 = *(const longlong2*)&KPs[dd][tx * 8];
            longlong2 kb1 = *(const longlong2*)&KPs[dd][tx * 8 + 4];
            ull B0 = (ull)kb0.x, B1 = (ull)kb0.y, B2 = (ull)kb1.x, B3 = (ull)kb1.y;
            float aa[4] = {qv.x, qv.y, qv.z, qv.w};
#pragma unroll
            for (int i = 0; i < 4; i++) {
                ull Am = pk2(aa[i], aa[i]);
                s2[i * 4 + 0] = fma2(Am, B0, s2[i * 4 + 0]);
                s2[i * 4 + 1] = fma2(Am, B1, s2[i * 4 + 1]);
                s2[i * 4 + 2] = fma2(Am, B2, s2[i * 4 + 2]);
                s2[i * 4 + 3] = fma2(Am, B3, s2[i * 4 + 3]);
            }
        }
        __syncthreads();   // all GEMM1 reads of KPs complete

        // exp (no max-sub; logits bounded), row sums, write P into KPs [k][q]
        float p[4][8];
#pragma unroll
        for (int i = 0; i < 4; i++) {
            float rs;
#pragma unroll
            for (int jp = 0; jp < 4; jp++) {
                float slo, shi;
                upk2(s2[i * 4 + jp], slo, shi);
                int kg = kbase + tx * 8 + jp * 2;
                p[i][jp * 2]     = (kg     < cnt) ? __expf(slo * 0.125f) : 0.f;
                p[i][jp * 2 + 1] = (kg + 1 < cnt) ? __expf(shi * 0.125f) : 0.f;
            }
            rs = ((p[i][0] + p[i][1]) + (p[i][2] + p[i][3]))
               + ((p[i][4] + p[i][5]) + (p[i][6] + p[i][7]));
            rs += __shfl_xor_sync(0xffffffffu, rs, 1);
            rs += __shfl_xor_sync(0xffffffffu, rs, 2);
            rs += __shfl_xor_sync(0xffffffffu, rs, 4);
            l[i] += rs;
        }
#pragma unroll
        for (int j = 0; j < 8; j++) {
            *(float4*)&KPs[tx * 8 + j][ty * 4] =
                make_float4(p[0][j], p[1][j], p[2][j], p[3][j]);
        }
        __syncthreads();

        // GEMM2: O[4q][8d] += sum_k P[k][q] * V[k][d]
#pragma unroll 4
        for (int kk = 0; kk < 64; kk++) {
            float4 pv = *(const float4*)&KPs[kk][ty * 4];
            longlong2 vb0 = *(const longlong2*)&Vs[kk][tx * 8];
            longlong2 vb1 = *(const longlong2*)&Vs[kk][tx * 8 + 4];
            ull B0 = (ull)vb0.x, B1 = (ull)vb0.y, B2 = (ull)vb1.x, B3 = (ull)vb1.y;
            float aa[4] = {pv.x, pv.y, pv.z, pv.w};
#pragma unroll
            for (int i = 0; i < 4; i++) {
                ull Am = pk2(aa[i], aa[i]);
                o2[i * 4 + 0] = fma2(Am, B0, o2[i * 4 + 0]);
                o2[i * 4 + 1] = fma2(Am, B1, o2[i * 4 + 1]);
                o2[i * 4 + 2] = fma2(Am, B2, o2[i * 4 + 2]);
                o2[i * 4 + 3] = fma2(Am, B3, o2[i * 4 + 3]);
            }
        }
    }

    // epilogue
#pragma unroll
    for (int i = 0; i < 4; i++) {
        int r = qbase + ty * 4 + i;
        if (r < cnt) {
            float inv = 1.0f / l[i];
            ull inv2 = pk2(inv, inv);
            float* dst = g_attnc + ((size_t)b * SS + r) * HH + n * DKK + tx * 8;
            float4 w0, w1;
            upk2(mul2(o2[i * 4 + 0], inv2), w0.x, w0.y);
            upk2(mul2(o2[i * 4 + 1], inv2), w0.z, w0.w);
            upk2(mul2(o2[i * 4 + 2], inv2), w1.x, w1.y);
            upk2(mul2(o2[i * 4 + 3], inv2), w1.z, w1.w);
            *(float4*)dst       = w0;
            *(float4*)(dst + 4) = w1;
        }
    }
}

// ---------------- 4) out projection: 128m x 64n tile, 8x8 micro ---------------
__global__ __launch_bounds__(128)
void outproj_kernel(const float* __restrict__ Wo,
                    float* __restrict__ out) {
    int nt = blockIdx.x;
    int b  = blockIdx.y >> 4;
    int mt = blockIdx.y & 15;
    int cnt = g_cnt[b];
    if (mt * 128 >= cnt) return;

    __shared__ __align__(16) float As[16][132];
    __shared__ __align__(16) float Bs[16][64];

    int t  = threadIdx.x;
    int tx = t & 7;
    int ty = t >> 3;

    const float* arow = g_attnc + ((size_t)b * SS + mt * 128 + t) * HH;
    int kk_b = t >> 3;
    int nn_b = (t & 7) * 8;

    ull acc[32];
#pragma unroll
    for (int i = 0; i < 32; i++) acc[i] = 0ULL;

    float4 a_r[4], b_r[2];
#pragma unroll
    for (int u = 0; u < 4; u++) a_r[u] = *(const float4*)(arow + u * 4);
    b_r[0] = *(const float4*)(Wo + (size_t)kk_b * HH + nt * 64 + nn_b);
    b_r[1] = *(const float4*)(Wo + (size_t)kk_b * HH + nt * 64 + nn_b + 4);

    for (int k0 = 0; k0 < HH; k0 += 16) {
        __syncthreads();
#pragma unroll
        for (int u = 0; u < 4; u++) {
            As[u * 4 + 0][t] = a_r[u].x;
            As[u * 4 + 1][t] = a_r[u].y;
            As[u * 4 + 2][t] = a_r[u].z;
            As[u * 4 + 3][t] = a_r[u].w;
        }
        *(float4*)&Bs[kk_b][nn_b]     = b_r[0];
        *(float4*)&Bs[kk_b][nn_b + 4] = b_r[1];
        __syncthreads();
        if (k0 + 16 < HH) {
#pragma unroll
            for (int u = 0; u < 4; u++) a_r[u] = *(const float4*)(arow + k0 + 16 + u * 4);
            b_r[0] = *(const float4*)(Wo + (size_t)(k0 + 16 + kk_b) * HH + nt * 64 + nn_b);
            b_r[1] = *(const float4*)(Wo + (size_t)(k0 + 16 + kk_b) * HH + nt * 64 + nn_b + 4);
        }
#pragma unroll
        for (int kk = 0; kk < 16; kk++) {
            float4 av0 = *(const float4*)&As[kk][ty * 8];
            float4 av1 = *(const float4*)&As[kk][ty * 8 + 4];
            longlong2 bb0 = *(const longlong2*)&Bs[kk][tx * 4];
            longlong2 bb1 = *(const longlong2*)&Bs[kk][32 + tx * 4];
            ull B0 = (ull)bb0.x, B1 = (ull)bb0.y, B2 = (ull)bb1.x, B3 = (ull)bb1.y;
            float am[8] = {av0.x, av0.y, av0.z, av0.w, av1.x, av1.y, av1.z, av1.w};
#pragma unroll
            for (int m = 0; m < 8; m++) {
                ull Am = pk2(am[m], am[m]);
                acc[m * 4 + 0] = fma2(Am, B0, acc[m * 4 + 0]);
                acc[m * 4 + 1] = fma2(Am, B1, acc[m * 4 + 1]);
                acc[m * 4 + 2] = fma2(Am, B2, acc[m * 4 + 2]);
                acc[m * 4 + 3] = fma2(Am, B3, acc[m * 4 + 3]);
            }
        }
    }
#pragma unroll
    for (int i = 0; i < 8; i++) {
        int r = mt * 128 + ty * 8 + i;
        if (r < cnt) {
            float o[8];
            upk2(acc[i * 4 + 0], o[0], o[1]);
            upk2(acc[i * 4 + 1], o[2], o[3]);
            upk2(acc[i * 4 + 2], o[4], o[5]);
            upk2(acc[i * 4 + 3], o[6], o[7]);
            int orig = g_idx[(size_t)b * SS + r];
            size_t rowoff = ((size_t)b * SS + orig) * HH + nt * 64;
            float4 x0 = *(const float4*)(g_xn + rowoff + tx * 4);
            float4 x1 = *(const float4*)(g_xn + rowoff + 32 + tx * 4);
            *(float4*)(out + rowoff + tx * 4) =
                make_float4(o[0] + x0.x, o[1] + x0.y, o[2] + x0.z, o[3] + x0.w);
            *(float4*)(out + rowoff + 32 + tx * 4) =
                make_float4(o[4] + x1.x, o[5] + x1.y, o[6] + x1.z, o[7] + x1.w);
        }
    }
}

// ---------------- launch ------------------------------------------------------
extern "C" void kernel_launch(void* const* d_in, const int* in_sizes, int n_in,
                              void* d_out, int out_size) {
    const float* x     = (const float*)d_in[0];
    const int*   mask  = (const int*)  d_in[1];
    const float* Wq    = (const float*)d_in[2];
    const float* Wk    = (const float*)d_in[3];
    const float* Wv    = (const float*)d_in[4];
    const float* Wo    = (const float*)d_in[5];
    const float* gamma = (const float*)d_in[6];
    const float* beta  = (const float*)d_in[7];
    float* out = (float*)d_out;

    zero_out_kernel<<<(BB * SS * HH) / (256 * 4), 256>>>(out);
    ln_kernel<<<BB * SS, 256>>>(x, gamma, beta);
    compact_kernel<<<BB, 256>>>(mask);
    qkv_kernel<<<dim3(SS / 128, 96), 128>>>(Wq, Wk, Wv);
    attn_kernel<<<dim3(SS / 64, BB * NH), 128>>>();
    outproj_kernel<<<dim3(HH / 64, BB * (SS / 128)), 128>>>(Wo, out);
}

// round 7
// speedup vs baseline: 3.6884x; 1.6583x over previous
#include <cuda_runtime.h>
#include <cuda_bf16.h>
#include <math.h>
#include <stdint.h>

#define BB 4
#define SS 2048
#define HH 512
#define NH 8
#define DKK 64

typedef unsigned long long ull;

// ---------------- f32x2 helpers (Blackwell packed fp32) ---------------------
__device__ __forceinline__ ull pk2(float lo, float hi) {
    ull r; asm("mov.b64 %0, {%1,%2};" : "=l"(r) : "f"(lo), "f"(hi)); return r;
}
__device__ __forceinline__ void upk2(ull v, float& lo, float& hi) {
    asm("mov.b64 {%0,%1}, %2;" : "=f"(lo), "=f"(hi) : "l"(v));
}
__device__ __forceinline__ ull fma2(ull a, ull b, ull c) {
    ull d; asm("fma.rn.f32x2 %0, %1, %2, %3;" : "=l"(d) : "l"(a), "l"(b), "l"(c)); return d;
}

// ---------------- mma.sync / ldmatrix helpers (baseline PTX, sm_80+) --------
__device__ __forceinline__ uint32_t packbf(float lo, float hi) {
    // returns {upper = bf16(hi), lower = bf16(lo)}
    uint32_t r; asm("cvt.rn.bf16x2.f32 %0, %2, %1;" : "=r"(r) : "f"(lo), "f"(hi)); return r;
}
__device__ __forceinline__ void pack_hl(float e0, float e1, uint32_t& h, uint32_t& l) {
    h = packbf(e0, e1);
    float a = __uint_as_float(h << 16);
    float b = __uint_as_float(h & 0xFFFF0000u);
    l = packbf(e0 - a, e1 - b);
}
__device__ __forceinline__ void ldsm4(uint32_t& r0, uint32_t& r1, uint32_t& r2, uint32_t& r3,
                                      uint32_t a) {
    asm volatile("ldmatrix.sync.aligned.m8n8.x4.shared.b16 {%0,%1,%2,%3}, [%4];"
                 : "=r"(r0), "=r"(r1), "=r"(r2), "=r"(r3) : "r"(a));
}
__device__ __forceinline__ void ldsm2(uint32_t& r0, uint32_t& r1, uint32_t a) {
    asm volatile("ldmatrix.sync.aligned.m8n8.x2.shared.b16 {%0,%1}, [%2];"
                 : "=r"(r0), "=r"(r1) : "r"(a));
}
__device__ __forceinline__ void ldsm2t(uint32_t& r0, uint32_t& r1, uint32_t a) {
    asm volatile("ldmatrix.sync.aligned.m8n8.x2.trans.shared.b16 {%0,%1}, [%2];"
                 : "=r"(r0), "=r"(r1) : "r"(a));
}
__device__ __forceinline__ void mma_bf16(float* c, uint32_t a0, uint32_t a1,
                                         uint32_t a2, uint32_t a3,
                                         uint32_t b0, uint32_t b1) {
    asm volatile(
        "mma.sync.aligned.m16n8k16.row.col.f32.bf16.bf16.f32 "
        "{%0,%1,%2,%3}, {%4,%5,%6,%7}, {%8,%9}, {%0,%1,%2,%3};"
        : "+f"(c[0]), "+f"(c[1]), "+f"(c[2]), "+f"(c[3])
        : "r"(a0), "r"(a1), "r"(a2), "r"(a3), "r"(b0), "r"(b1));
}

// ---------------- scratch ----------------------------------------------------
__device__ float g_xn[BB * SS * HH];
__device__ float g_qc[BB * NH * SS * DKK];
__device__ float g_kc[BB * NH * SS * DKK];
__device__ float g_vc[BB * NH * SS * DKK];
__device__ float g_attnc[BB * SS * HH];
__device__ int   g_idx[BB * SS];
__device__ int   g_cnt[BB];

// ---------------- 1) LayerNorm ----------------------------------------------
__global__ void ln_kernel(const float* __restrict__ x,
                          const float* __restrict__ gamma,
                          const float* __restrict__ beta) {
    int row = blockIdx.x;
    const float* xr = x + (size_t)row * HH;
    int t = threadIdx.x;
    float a = xr[t];
    float b = xr[t + 256];
    float s  = a + b;
    float sq = a * a + b * b;
    __shared__ float ssum[8], ssq[8];
    for (int o = 16; o > 0; o >>= 1) {
        s  += __shfl_xor_sync(0xffffffffu, s,  o);
        sq += __shfl_xor_sync(0xffffffffu, sq, o);
    }
    if ((t & 31) == 0) { ssum[t >> 5] = s; ssq[t >> 5] = sq; }
    __syncthreads();
    float tot = 0.f, totq = 0.f;
#pragma unroll
    for (int i = 0; i < 8; i++) { tot += ssum[i]; totq += ssq[i]; }
    float mu  = tot * (1.0f / HH);
    float var = totq * (1.0f / HH) - mu * mu;
    float inv = rsqrtf(var + 1e-5f);
    float* dst = g_xn + (size_t)row * HH;
    dst[t]       = (a - mu) * inv * gamma[t]       + beta[t];
    dst[t + 256] = (b - mu) * inv * gamma[t + 256] + beta[t + 256];
}

// ---------------- 1b) mask compaction ----------------------------------------
__global__ void compact_kernel(const int* __restrict__ mask) {
    int b = blockIdx.x;
    int t = threadIdx.x;
    int vals[8];
    int c = 0;
#pragma unroll
    for (int i = 0; i < 8; i++) {
        vals[i] = mask[(size_t)b * SS + t * 8 + i];
        c += (vals[i] != 0);
    }
    __shared__ int s[256];
    s[t] = c;
    __syncthreads();
    for (int off = 1; off < 256; off <<= 1) {
        int v = (t >= off) ? s[t - off] : 0;
        __syncthreads();
        s[t] += v;
        __syncthreads();
    }
    int pos = s[t] - c;
#pragma unroll
    for (int i = 0; i < 8; i++) {
        if (vals[i]) g_idx[(size_t)b * SS + (pos++)] = t * 8 + i;
    }
    if (t == 255) g_cnt[b] = s[255];
}

// ---------------- 1c) zero output ---------------------------------------------
__global__ void zero_out_kernel(float* __restrict__ out) {
    int i = blockIdx.x * blockDim.x + threadIdx.x;
    ((float4*)out)[i] = make_float4(0.f, 0.f, 0.f, 0.f);
}

// ---------------- 2) QKV projection (unchanged, known good) -------------------
__global__ __launch_bounds__(128)
void qkv_kernel(const float* __restrict__ Wq,
                const float* __restrict__ Wk,
                const float* __restrict__ Wv) {
    int mt    = blockIdx.x;
    int which = blockIdx.y >> 5;
    int bn    = blockIdx.y & 31;
    int b = bn >> 3, n = bn & 7;
    int cnt = g_cnt[b];
    if (mt * 128 >= cnt) return;

    const float* W = (which == 0 ? Wq : (which == 1 ? Wk : Wv)) + (size_t)n * HH * DKK;
    float* Cout    = (which == 0 ? g_qc : (which == 1 ? g_kc : g_vc)) + (size_t)bn * SS * DKK;

    __shared__ __align__(16) float As[16][132];
    __shared__ __align__(16) float Bs[16][64];

    int t  = threadIdx.x;
    int tx = t & 7;
    int ty = t >> 3;

    int gm = mt * 128 + t;
    int om = g_idx[(size_t)b * SS + (gm < cnt ? gm : cnt - 1)];
    const float* arow = g_xn + ((size_t)b * SS + om) * HH;
    int kk_b = t >> 3;
    int nn_b = (t & 7) * 8;

    ull acc[32];
#pragma unroll
    for (int i = 0; i < 32; i++) acc[i] = 0ULL;

    float4 a_r[4], b_r[2];
#pragma unroll
    for (int u = 0; u < 4; u++) a_r[u] = *(const float4*)(arow + u * 4);
    b_r[0] = *(const float4*)(W + (size_t)kk_b * DKK + nn_b);
    b_r[1] = *(const float4*)(W + (size_t)kk_b * DKK + nn_b + 4);

    for (int k0 = 0; k0 < HH; k0 += 16) {
        __syncthreads();
#pragma unroll
        for (int u = 0; u < 4; u++) {
            As[u * 4 + 0][t] = a_r[u].x;
            As[u * 4 + 1][t] = a_r[u].y;
            As[u * 4 + 2][t] = a_r[u].z;
            As[u * 4 + 3][t] = a_r[u].w;
        }
        *(float4*)&Bs[kk_b][nn_b]     = b_r[0];
        *(float4*)&Bs[kk_b][nn_b + 4] = b_r[1];
        __syncthreads();
        if (k0 + 16 < HH) {
#pragma unroll
            for (int u = 0; u < 4; u++) a_r[u] = *(const float4*)(arow + k0 + 16 + u * 4);
            b_r[0] = *(const float4*)(W + (size_t)(k0 + 16 + kk_b) * DKK + nn_b);
            b_r[1] = *(const float4*)(W + (size_t)(k0 + 16 + kk_b) * DKK + nn_b + 4);
        }
#pragma unroll
        for (int kk = 0; kk < 16; kk++) {
            float4 av0 = *(const float4*)&As[kk][ty * 8];
            float4 av1 = *(const float4*)&As[kk][ty * 8 + 4];
            longlong2 bb0 = *(const longlong2*)&Bs[kk][tx * 4];
            longlong2 bb1 = *(const longlong2*)&Bs[kk][32 + tx * 4];
            ull B0 = (ull)bb0.x, B1 = (ull)bb0.y, B2 = (ull)bb1.x, B3 = (ull)bb1.y;
            float am[8] = {av0.x, av0.y, av0.z, av0.w, av1.x, av1.y, av1.z, av1.w};
#pragma unroll
            for (int m = 0; m < 8; m++) {
                ull Am = pk2(am[m], am[m]);
                acc[m * 4 + 0] = fma2(Am, B0, acc[m * 4 + 0]);
                acc[m * 4 + 1] = fma2(Am, B1, acc[m * 4 + 1]);
                acc[m * 4 + 2] = fma2(Am, B2, acc[m * 4 + 2]);
                acc[m * 4 + 3] = fma2(Am, B3, acc[m * 4 + 3]);
            }
        }
    }
#pragma unroll
    for (int i = 0; i < 8; i++) {
        int r = mt * 128 + ty * 8 + i;
        if (r < cnt) {
            float o[8];
            upk2(acc[i * 4 + 0], o[0], o[1]);
            upk2(acc[i * 4 + 1], o[2], o[3]);
            upk2(acc[i * 4 + 2], o[4], o[5]);
            upk2(acc[i * 4 + 3], o[6], o[7]);
            float* dst = Cout + (size_t)r * DKK;
            *(float4*)(dst + tx * 4)      = make_float4(o[0], o[1], o[2], o[3]);
            *(float4*)(dst + 32 + tx * 4) = make_float4(o[4], o[5], o[6], o[7]);
        }
    }
}

// ---------------- 3) attention: mma.sync bf16-split ---------------------------
// grid (32 q-tiles of 64, 32 bn), 128 threads (4 warps x 16 q rows).
#define APAD 72
#define OFF_QHI 0
#define OFF_QLO 9216
#define OFF_KHI 18432
#define OFF_KLO 27648
#define OFF_VHI 36864
#define OFF_VLO 46080
#define SMA_TOTAL 55296

__global__ __launch_bounds__(128)
void attn_kernel() {
    extern __shared__ __align__(16) char sm[];
    int bn = blockIdx.y;
    int b  = bn >> 3;
    int n  = bn & 7;
    int cnt = g_cnt[b];
    int qbase = blockIdx.x * 64;
    if (qbase >= cnt) return;

    int tid  = threadIdx.x;
    int w    = tid >> 5;
    int lane = tid & 31;
    int g    = lane >> 2;
    int tig  = lane & 3;
    uint32_t sb = (uint32_t)__cvta_generic_to_shared(sm);

    // ---- stage Q tile (bf16 hi/lo, padded rows) -------------------------------
    {
        int row = tid >> 1;
        int dh  = (tid & 1) * 32;
        const float* src = g_qc + ((size_t)bn * SS + qbase + row) * DKK + dh;
#pragma unroll
        for (int c = 0; c < 4; c++) {
            float4 f0 = *(const float4*)(src + c * 8);
            float4 f1 = *(const float4*)(src + c * 8 + 4);
            uint32_t h[4], l[4];
            pack_hl(f0.x, f0.y, h[0], l[0]);
            pack_hl(f0.z, f0.w, h[1], l[1]);
            pack_hl(f1.x, f1.y, h[2], l[2]);
            pack_hl(f1.z, f1.w, h[3], l[3]);
            uint32_t off = (uint32_t)(row * APAD + dh + c * 8) * 2;
            *(uint4*)(sm + OFF_QHI + off) = make_uint4(h[0], h[1], h[2], h[3]);
            *(uint4*)(sm + OFF_QLO + off) = make_uint4(l[0], l[1], l[2], l[3]);
        }
    }

    float o[8][4];
#pragma unroll
    for (int i = 0; i < 8; i++)
#pragma unroll
        for (int j = 0; j < 4; j++) o[i][j] = 0.f;
    float l0 = 0.f, l1 = 0.f;

    int q0 = w * 16;
    // per-thread ldmatrix source coordinates
    int arow_q = q0 + (lane & 7) + ((lane >> 3) & 1) * 8;   // A tiles 0/1 rows, 2/3 same
    int ad_sel = (lane >> 4) * 8;                            // tiles 2,3 use +8 in d
    int brow   = lane & 7;
    int bsel   = ((lane >> 3) & 1) * 8;

    int ktiles = (cnt + 63) >> 6;
    for (int kt = 0; kt < ktiles; kt++) {
        int kbase = kt * 64;
        __syncthreads();   // prior tile's compute done before overwriting K/V
        // ---- stage K and V tiles ----------------------------------------------
        {
            int row = tid >> 1;
            int dh  = (tid & 1) * 32;
            const float* ks = g_kc + ((size_t)bn * SS + kbase + row) * DKK + dh;
            const float* vs = g_vc + ((size_t)bn * SS + kbase + row) * DKK + dh;
#pragma unroll
            for (int c = 0; c < 4; c++) {
                float4 f0 = *(const float4*)(ks + c * 8);
                float4 f1 = *(const float4*)(ks + c * 8 + 4);
                uint32_t h[4], l[4];
                pack_hl(f0.x, f0.y, h[0], l[0]);
                pack_hl(f0.z, f0.w, h[1], l[1]);
                pack_hl(f1.x, f1.y, h[2], l[2]);
                pack_hl(f1.z, f1.w, h[3], l[3]);
                uint32_t off = (uint32_t)(row * APAD + dh + c * 8) * 2;
                *(uint4*)(sm + OFF_KHI + off) = make_uint4(h[0], h[1], h[2], h[3]);
                *(uint4*)(sm + OFF_KLO + off) = make_uint4(l[0], l[1], l[2], l[3]);
            }
#pragma unroll
            for (int c = 0; c < 4; c++) {
                float4 f0 = *(const float4*)(vs + c * 8);
                float4 f1 = *(const float4*)(vs + c * 8 + 4);
                uint32_t h[4], l[4];
                pack_hl(f0.x, f0.y, h[0], l[0]);
                pack_hl(f0.z, f0.w, h[1], l[1]);
                pack_hl(f1.x, f1.y, h[2], l[2]);
                pack_hl(f1.z, f1.w, h[3], l[3]);
                uint32_t off = (uint32_t)(row * APAD + dh + c * 8) * 2;
                *(uint4*)(sm + OFF_VHI + off) = make_uint4(h[0], h[1], h[2], h[3]);
                *(uint4*)(sm + OFF_VLO + off) = make_uint4(l[0], l[1], l[2], l[3]);
            }
        }
        __syncthreads();

        // ---- S = Q.K^T (split bf16) -------------------------------------------
        float s[8][4];
#pragma unroll
        for (int i = 0; i < 8; i++)
#pragma unroll
            for (int j = 0; j < 4; j++) s[i][j] = 0.f;

#pragma unroll
        for (int c = 0; c < 4; c++) {
            uint32_t aoffq = (uint32_t)(arow_q * APAD + 16 * c + ad_sel) * 2;
            uint32_t ah0, ah1, ah2, ah3, al0, al1, al2, al3;
            ldsm4(ah0, ah1, ah2, ah3, sb + OFF_QHI + aoffq);
            ldsm4(al0, al1, al2, al3, sb + OFF_QLO + aoffq);
#pragma unroll
            for (int j = 0; j < 8; j++) {
                uint32_t boff = (uint32_t)((8 * j + brow) * APAD + 16 * c + bsel) * 2;
                uint32_t bh0, bh1, bl0, bl1;
                ldsm2(bh0, bh1, sb + OFF_KHI + boff);
                ldsm2(bl0, bl1, sb + OFF_KLO + boff);
                mma_bf16(s[j], ah0, ah1, ah2, ah3, bh0, bh1);
                mma_bf16(s[j], al0, al1, al2, al3, bh0, bh1);
                mma_bf16(s[j], ah0, ah1, ah2, ah3, bl0, bl1);
            }
        }

        // ---- softmax (no max-sub; masked keys -> p=0) --------------------------
#pragma unroll
        for (int j = 0; j < 8; j++) {
            int kg0 = kbase + 8 * j + 2 * tig;
#pragma unroll
            for (int r = 0; r < 4; r++) {
                int kg = kg0 + (r & 1);
                float p = (kg < cnt) ? __expf(s[j][r] * 0.125f) : 0.f;
                s[j][r] = p;
                if (r < 2) l0 += p; else l1 += p;
            }
        }

        // ---- O += P.V (P stays in registers as A fragments) --------------------
#pragma unroll
        for (int c = 0; c < 4; c++) {
            uint32_t ph0, ph1, ph2, ph3, pl0, pl1, pl2, pl3;
            pack_hl(s[2 * c][0],     s[2 * c][1],     ph0, pl0);
            pack_hl(s[2 * c][2],     s[2 * c][3],     ph1, pl1);
            pack_hl(s[2 * c + 1][0], s[2 * c + 1][1], ph2, pl2);
            pack_hl(s[2 * c + 1][2], s[2 * c + 1][3], ph3, pl3);
#pragma unroll
            for (int dt = 0; dt < 8; dt++) {
                uint32_t voff = (uint32_t)((16 * c + bsel + brow) * APAD + 8 * dt) * 2;
                uint32_t vh0, vh1, vl0, vl1;
                ldsm2t(vh0, vh1, sb + OFF_VHI + voff);
                ldsm2t(vl0, vl1, sb + OFF_VLO + voff);
                mma_bf16(o[dt], ph0, ph1, ph2, ph3, vh0, vh1);
                mma_bf16(o[dt], pl0, pl1, pl2, pl3, vh0, vh1);
                mma_bf16(o[dt], ph0, ph1, ph2, ph3, vl0, vl1);
            }
        }
    }

    // ---- epilogue --------------------------------------------------------------
    l0 += __shfl_xor_sync(0xffffffffu, l0, 1);
    l0 += __shfl_xor_sync(0xffffffffu, l0, 2);
    l1 += __shfl_xor_sync(0xffffffffu, l1, 1);
    l1 += __shfl_xor_sync(0xffffffffu, l1, 2);
    float inv0 = 1.0f / l0;
    float inv1 = 1.0f / l1;

    int r0 = qbase + q0 + g;
    int r1 = r0 + 8;
    size_t base0 = ((size_t)b * SS + r0) * HH + n * DKK + 2 * tig;
    size_t base1 = ((size_t)b * SS + r1) * HH + n * DKK + 2 * tig;
#pragma unroll
    for (int dt = 0; dt < 8; dt++) {
        if (r0 < cnt)
            *(float2*)(g_attnc + base0 + 8 * dt) =
                make_float2(o[dt][0] * inv0, o[dt][1] * inv0);
        if (r1 < cnt)
            *(float2*)(g_attnc + base1 + 8 * dt) =
                make_float2(o[dt][2] * inv1, o[dt][3] * inv1);
    }
}

// ---------------- 4) out projection (unchanged, known good) -------------------
__global__ __launch_bounds__(128)
void outproj_kernel(const float* __restrict__ Wo,
                    float* __restrict__ out) {
    int nt = blockIdx.x;
    int b  = blockIdx.y >> 4;
    int mt = blockIdx.y & 15;
    int cnt = g_cnt[b];
    if (mt * 128 >= cnt) return;

    __shared__ __align__(16) float As[16][132];
    __shared__ __align__(16) float Bs[16][64];

    int t  = threadIdx.x;
    int tx = t & 7;
    int ty = t >> 3;

    const float* arow = g_attnc + ((size_t)b * SS + mt * 128 + t) * HH;
    int kk_b = t >> 3;
    int nn_b = (t & 7) * 8;

    ull acc[32];
#pragma unroll
    for (int i = 0; i < 32; i++) acc[i] = 0ULL;

    float4 a_r[4], b_r[2];
#pragma unroll
    for (int u = 0; u < 4; u++) a_r[u] = *(const float4*)(arow + u * 4);
    b_r[0] = *(const float4*)(Wo + (size_t)kk_b * HH + nt * 64 + nn_b);
    b_r[1] = *(const float4*)(Wo + (size_t)kk_b * HH + nt * 64 + nn_b + 4);

    for (int k0 = 0; k0 < HH; k0 += 16) {
        __syncthreads();
#pragma unroll
        for (int u = 0; u < 4; u++) {
            As[u * 4 + 0][t] = a_r[u].x;
            As[u * 4 + 1][t] = a_r[u].y;
            As[u * 4 + 2][t] = a_r[u].z;
            As[u * 4 + 3][t] = a_r[u].w;
        }
        *(float4*)&Bs[kk_b][nn_b]     = b_r[0];
        *(float4*)&Bs[kk_b][nn_b + 4] = b_r[1];
        __syncthreads();
        if (k0 + 16 < HH) {
#pragma unroll
            for (int u = 0; u < 4; u++) a_r[u] = *(const float4*)(arow + k0 + 16 + u * 4);
            b_r[0] = *(const float4*)(Wo + (size_t)(k0 + 16 + kk_b) * HH + nt * 64 + nn_b);
            b_r[1] = *(const float4*)(Wo + (size_t)(k0 + 16 + kk_b) * HH + nt * 64 + nn_b + 4);
        }
#pragma unroll
        for (int kk = 0; kk < 16; kk++) {
            float4 av0 = *(const float4*)&As[kk][ty * 8];
            float4 av1 = *(const float4*)&As[kk][ty * 8 + 4];
            longlong2 bb0 = *(const longlong2*)&Bs[kk][tx * 4];
            longlong2 bb1 = *(const longlong2*)&Bs[kk][32 + tx * 4];
            ull B0 = (ull)bb0.x, B1 = (ull)bb0.y, B2 = (ull)bb1.x, B3 = (ull)bb1.y;
            float am[8] = {av0.x, av0.y, av0.z, av0.w, av1.x, av1.y, av1.z, av1.w};
#pragma unroll
            for (int m = 0; m < 8; m++) {
                ull Am = pk2(am[m], am[m]);
                acc[m * 4 + 0] = fma2(Am, B0, acc[m * 4 + 0]);
                acc[m * 4 + 1] = fma2(Am, B1, acc[m * 4 + 1]);
                acc[m * 4 + 2] = fma2(Am, B2, acc[m * 4 + 2]);
                acc[m * 4 + 3] = fma2(Am, B3, acc[m * 4 + 3]);
            }
        }
    }
#pragma unroll
    for (int i = 0; i < 8; i++) {
        int r = mt * 128 + ty * 8 + i;
        if (r < cnt) {
            float o[8];
            upk2(acc[i * 4 + 0], o[0], o[1]);
            upk2(acc[i * 4 + 1], o[2], o[3]);
            upk2(acc[i * 4 + 2], o[4], o[5]);
            upk2(acc[i * 4 + 3], o[6], o[7]);
            int orig = g_idx[(size_t)b * SS + r];
            size_t rowoff = ((size_t)b * SS + orig) * HH + nt * 64;
            float4 x0 = *(const float4*)(g_xn + rowoff + tx * 4);
            float4 x1 = *(const float4*)(g_xn + rowoff + 32 + tx * 4);
            *(float4*)(out + rowoff + tx * 4) =
                make_float4(o[0] + x0.x, o[1] + x0.y, o[2] + x0.z, o[3] + x0.w);
            *(float4*)(out + rowoff + 32 + tx * 4) =
                make_float4(o[4] + x1.x, o[5] + x1.y, o[6] + x1.z, o[7] + x1.w);
        }
    }
}

// ---------------- launch ------------------------------------------------------
extern "C" void kernel_launch(void* const* d_in, const int* in_sizes, int n_in,
                              void* d_out, int out_size) {
    const float* x     = (const float*)d_in[0];
    const int*   mask  = (const int*)  d_in[1];
    const float* Wq    = (const float*)d_in[2];
    const float* Wk    = (const float*)d_in[3];
    const float* Wv    = (const float*)d_in[4];
    const float* Wo    = (const float*)d_in[5];
    const float* gamma = (const float*)d_in[6];
    const float* beta  = (const float*)d_in[7];
    float* out = (float*)d_out;

    cudaFuncSetAttribute(attn_kernel,
                         cudaFuncAttributeMaxDynamicSharedMemorySize, SMA_TOTAL);

    zero_out_kernel<<<(BB * SS * HH) / (256 * 4), 256>>>(out);
    ln_kernel<<<BB * SS, 256>>>(x, gamma, beta);
    compact_kernel<<<BB, 256>>>(mask);
    qkv_kernel<<<dim3(SS / 128, 96), 128>>>(Wq, Wk, Wv);
    attn_kernel<<<dim3(SS / 64, BB * NH), 128, SMA_TOTAL>>>();
    outproj_kernel<<<dim3(HH / 64, BB * (SS / 128)), 128>>>(Wo, out);
}

// round 9
// speedup vs baseline: 4.7742x; 1.2944x over previous
#include <cuda_runtime.h>
#include <cuda_bf16.h>
#include <math.h>
#include <stdint.h>

#define BB 4
#define SS 2048
#define HH 512
#define NH 8
#define DKK 64

typedef unsigned long long ull;

// ---------------- bf16 split + mma.sync helpers (baseline PTX) ---------------
__device__ __forceinline__ uint32_t packbf(float lo, float hi) {
    uint32_t r; asm("cvt.rn.bf16x2.f32 %0, %2, %1;" : "=r"(r) : "f"(lo), "f"(hi)); return r;
}
__device__ __forceinline__ void pack_hl(float e0, float e1, uint32_t& h, uint32_t& l) {
    h = packbf(e0, e1);
    float a = __uint_as_float(h << 16);
    float b = __uint_as_float(h & 0xFFFF0000u);
    l = packbf(e0 - a, e1 - b);
}
__device__ __forceinline__ void ldsm4(uint32_t& r0, uint32_t& r1, uint32_t& r2, uint32_t& r3,
                                      uint32_t a) {
    asm volatile("ldmatrix.sync.aligned.m8n8.x4.shared.b16 {%0,%1,%2,%3}, [%4];"
                 : "=r"(r0), "=r"(r1), "=r"(r2), "=r"(r3) : "r"(a));
}
__device__ __forceinline__ void ldsm2(uint32_t& r0, uint32_t& r1, uint32_t a) {
    asm volatile("ldmatrix.sync.aligned.m8n8.x2.shared.b16 {%0,%1}, [%2];"
                 : "=r"(r0), "=r"(r1) : "r"(a));
}
__device__ __forceinline__ void ldsm2t(uint32_t& r0, uint32_t& r1, uint32_t a) {
    asm volatile("ldmatrix.sync.aligned.m8n8.x2.trans.shared.b16 {%0,%1}, [%2];"
                 : "=r"(r0), "=r"(r1) : "r"(a));
}
__device__ __forceinline__ void mma_bf16(float* c, uint32_t a0, uint32_t a1,
                                         uint32_t a2, uint32_t a3,
                                         uint32_t b0, uint32_t b1) {
    asm volatile(
        "mma.sync.aligned.m16n8k16.row.col.f32.bf16.bf16.f32 "
        "{%0,%1,%2,%3}, {%4,%5,%6,%7}, {%8,%9}, {%0,%1,%2,%3};"
        : "+f"(c[0]), "+f"(c[1]), "+f"(c[2]), "+f"(c[3])
        : "r"(a0), "r"(a1), "r"(a2), "r"(a3), "r"(b0), "r"(b1));
}

// ---------------- scratch ----------------------------------------------------
__device__ float g_xn[BB * SS * HH];
__device__ float g_qc[BB * NH * SS * DKK];
__device__ float g_kc[BB * NH * SS * DKK];
__device__ float g_vc[BB * NH * SS * DKK];
__device__ float g_attnc[BB * SS * HH];
__device__ int   g_idx[BB * SS];
__device__ int   g_cnt[BB];

// bf16-split staging buffers (u32 = packed bf16 pair along contiguous axis)
#define WQ_OFF 0
#define WK_OFF 131072
#define WV_OFF 262144
#define WO_OFF 393216
#define WALL   524288
__device__ uint32_t g_whi[WALL], g_wlo[WALL];
__device__ uint32_t g_xhi[BB * SS * 256], g_xlo[BB * SS * 256];   // compacted xn
__device__ uint32_t g_ahi[BB * SS * 256], g_alo[BB * SS * 256];   // compacted attn out

// ---------------- 1) LayerNorm ----------------------------------------------
__global__ void ln_kernel(const float* __restrict__ x,
                          const float* __restrict__ gamma,
                          const float* __restrict__ beta) {
    int row = blockIdx.x;
    const float* xr = x + (size_t)row * HH;
    int t = threadIdx.x;
    float a = xr[t];
    float b = xr[t + 256];
    float s  = a + b;
    float sq = a * a + b * b;
    __shared__ float ssum[8], ssq[8];
    for (int o = 16; o > 0; o >>= 1) {
        s  += __shfl_xor_sync(0xffffffffu, s,  o);
        sq += __shfl_xor_sync(0xffffffffu, sq, o);
    }
    if ((t & 31) == 0) { ssum[t >> 5] = s; ssq[t >> 5] = sq; }
    __syncthreads();
    float tot = 0.f, totq = 0.f;
#pragma unroll
    for (int i = 0; i < 8; i++) { tot += ssum[i]; totq += ssq[i]; }
    float mu  = tot * (1.0f / HH);
    float var = totq * (1.0f / HH) - mu * mu;
    float inv = rsqrtf(var + 1e-5f);
    float* dst = g_xn + (size_t)row * HH;
    dst[t]       = (a - mu) * inv * gamma[t]       + beta[t];
    dst[t + 256] = (b - mu) * inv * gamma[t + 256] + beta[t + 256];
}

// ---------------- 1b) mask compaction ----------------------------------------
__global__ void compact_kernel(const int* __restrict__ mask) {
    int b = blockIdx.x;
    int t = threadIdx.x;
    int vals[8];
    int c = 0;
#pragma unroll
    for (int i = 0; i < 8; i++) {
        vals[i] = mask[(size_t)b * SS + t * 8 + i];
        c += (vals[i] != 0);
    }
    __shared__ int s[256];
    s[t] = c;
    __syncthreads();
    for (int off = 1; off < 256; off <<= 1) {
        int v = (t >= off) ? s[t - off] : 0;
        __syncthreads();
        s[t] += v;
        __syncthreads();
    }
    int pos = s[t] - c;
#pragma unroll
    for (int i = 0; i < 8; i++) {
        if (vals[i]) g_idx[(size_t)b * SS + (pos++)] = t * 8 + i;
    }
    if (t == 255) g_cnt[b] = s[255];
}

// ---------------- 1c) zero output ---------------------------------------------
__global__ void zero_out_kernel(float* __restrict__ out) {
    int i = blockIdx.x * blockDim.x + threadIdx.x;
    ((float4*)out)[i] = make_float4(0.f, 0.f, 0.f, 0.f);
}

// ---------------- 1d) weight convert (fp32 -> bf16 hi/lo) ---------------------
__global__ void wcvt_kernel(const float* __restrict__ Wq, const float* __restrict__ Wk,
                            const float* __restrict__ Wv, const float* __restrict__ Wo) {
    int i = blockIdx.x * 256 + threadIdx.x;       // 0..524287
    const float* src;
    int rem;
    if (i < WO_OFF) {
        int which = i / 131072;
        rem = i - which * 131072;
        src = (which == 0 ? Wq : (which == 1 ? Wk : Wv));
    } else {
        rem = i - WO_OFF;
        src = Wo;
    }
    float2 v = *(const float2*)(src + (size_t)rem * 2);
    uint32_t h, l;
    pack_hl(v.x, v.y, h, l);
    g_whi[i] = h;
    g_wlo[i] = l;
}

// ---------------- 1e) xn convert + gather (compacted) -------------------------
__global__ void xcvt_kernel() {
    int b = blockIdx.y, r = blockIdx.x;
    if (r >= g_cnt[b]) return;
    int orig = g_idx[(size_t)b * SS + r];
    const float* src = g_xn + ((size_t)b * SS + orig) * HH;
    int t = threadIdx.x;        // 128, 4 floats each
    float4 v = *(const float4*)(src + t * 4);
    uint32_t h0, l0, h1, l1;
    pack_hl(v.x, v.y, h0, l0);
    pack_hl(v.z, v.w, h1, l1);
    size_t o = ((size_t)b * SS + r) * 256 + t * 2;
    g_xhi[o] = h0; g_xhi[o + 1] = h1;
    g_xlo[o] = l0; g_xlo[o + 1] = l1;
}

// ---------------- 1f) attn-out convert (already compacted) --------------------
__global__ void acvt_kernel() {
    int b = blockIdx.y, r = blockIdx.x;
    if (r >= g_cnt[b]) return;
    const float* src = g_attnc + ((size_t)b * SS + r) * HH;
    int t = threadIdx.x;
    float4 v = *(const float4*)(src + t * 4);
    uint32_t h0, l0, h1, l1;
    pack_hl(v.x, v.y, h0, l0);
    pack_hl(v.z, v.w, h1, l1);
    size_t o = ((size_t)b * SS + r) * 256 + t * 2;
    g_ahi[o] = h0; g_ahi[o + 1] = h1;
    g_alo[o] = l0; g_alo[o + 1] = l1;
}

// ---------------- 2) QKV projection via mma.sync ------------------------------
// grid (32 m-tiles of 64 -> full 2048 rows, 96 = which*32 + bn), 128 threads
__global__ __launch_bounds__(128)
void qkv_mma_kernel() {
    int mt    = blockIdx.x;                // 0..31  (64 rows each = 2048)
    int which = blockIdx.y >> 5;
    int bn    = blockIdx.y & 31;
    int b = bn >> 3, n = bn & 7;
    int cnt = g_cnt[b];
    if (mt * 64 >= cnt) return;

    const uint32_t* Wh = g_whi + which * 131072 + n * 16384;   // [512][32] u32
    const uint32_t* Wl = g_wlo + which * 131072 + n * 16384;
    float* Cout = (which == 0 ? g_qc : (which == 1 ? g_kc : g_vc)) + (size_t)bn * SS * DKK;

    __shared__ __align__(16) uint32_t sAhi[64 * 36], sAlo[64 * 36];
    __shared__ __align__(16) uint32_t sWhi[64 * 36], sWlo[64 * 36];

    int tid  = threadIdx.x;
    int w    = tid >> 5;
    int lane = tid & 31;
    int g    = lane >> 2;
    int tig  = lane & 3;
    int arow = w * 16 + (lane & 7) + ((lane >> 3) & 1) * 8;
    int ad   = (lane >> 4) * 8;
    int brow = (lane & 7) + ((lane >> 3) & 1) * 8;

    uint32_t bAhi = (uint32_t)__cvta_generic_to_shared(sAhi);
    uint32_t bAlo = (uint32_t)__cvta_generic_to_shared(sAlo);
    uint32_t bWhi = (uint32_t)__cvta_generic_to_shared(sWhi);
    uint32_t bWlo = (uint32_t)__cvta_generic_to_shared(sWlo);

    float acc[8][4];
#pragma unroll
    for (int i = 0; i < 8; i++)
#pragma unroll
        for (int j = 0; j < 4; j++) acc[i][j] = 0.f;

    int lrow  = tid >> 1;
    int lhalf = (tid & 1) * 16;
    const uint32_t* aH = g_xhi + ((size_t)b * SS + mt * 64 + lrow) * 256 + lhalf;
    const uint32_t* aL = g_xlo + ((size_t)b * SS + mt * 64 + lrow) * 256 + lhalf;

    for (int kc = 0; kc < 8; kc++) {
        __syncthreads();
        const uint32_t* wH = Wh + (kc * 64 + lrow) * 32 + lhalf;
        const uint32_t* wL = Wl + (kc * 64 + lrow) * 32 + lhalf;
#pragma unroll
        for (int j = 0; j < 4; j++) {
            *(uint4*)&sAhi[lrow * 36 + lhalf + 4 * j] = *(const uint4*)(aH + kc * 32 + 4 * j);
            *(uint4*)&sAlo[lrow * 36 + lhalf + 4 * j] = *(const uint4*)(aL + kc * 32 + 4 * j);
            *(uint4*)&sWhi[lrow * 36 + lhalf + 4 * j] = *(const uint4*)(wH + 4 * j);
            *(uint4*)&sWlo[lrow * 36 + lhalf + 4 * j] = *(const uint4*)(wL + 4 * j);
        }
        __syncthreads();
#pragma unroll
        for (int c = 0; c < 4; c++) {
            uint32_t aoff = (uint32_t)(arow * 72 + 16 * c + ad) * 2;
            uint32_t ah0, ah1, ah2, ah3, al0, al1, al2, al3;
            ldsm4(ah0, ah1, ah2, ah3, bAhi + aoff);
            ldsm4(al0, al1, al2, al3, bAlo + aoff);
#pragma unroll
            for (int nt = 0; nt < 8; nt++) {
                uint32_t boff = (uint32_t)((16 * c + brow) * 72 + 8 * nt) * 2;
                uint32_t bh0, bh1, bl0, bl1;
                ldsm2t(bh0, bh1, bWhi + boff);
                ldsm2t(bl0, bl1, bWlo + boff);
                mma_bf16(acc[nt], ah0, ah1, ah2, ah3, bh0, bh1);
                mma_bf16(acc[nt], al0, al1, al2, al3, bh0, bh1);
                mma_bf16(acc[nt], ah0, ah1, ah2, ah3, bl0, bl1);
            }
        }
    }
    int r0 = mt * 64 + w * 16 + g;
    int r1 = r0 + 8;
#pragma unroll
    for (int nt = 0; nt < 8; nt++) {
        int col = nt * 8 + 2 * tig;
        if (r0 < cnt) *(float2*)(Cout + (size_t)r0 * DKK + col) = make_float2(acc[nt][0], acc[nt][1]);
        if (r1 < cnt) *(float2*)(Cout + (size_t)r1 * DKK + col) = make_float2(acc[nt][2], acc[nt][3]);
    }
}

// ---------------- 3) attention: mma.sync bf16-split (unchanged, known good) ---
#define APAD 72
#define OFF_QHI 0
#define OFF_QLO 9216
#define OFF_KHI 18432
#define OFF_KLO 27648
#define OFF_VHI 36864
#define OFF_VLO 46080
#define SMA_TOTAL 55296

__global__ __launch_bounds__(128)
void attn_kernel() {
    extern __shared__ __align__(16) char sm[];
    int bn = blockIdx.y;
    int b  = bn >> 3;
    int n  = bn & 7;
    int cnt = g_cnt[b];
    int qbase = blockIdx.x * 64;
    if (qbase >= cnt) return;

    int tid  = threadIdx.x;
    int w    = tid >> 5;
    int lane = tid & 31;
    int g    = lane >> 2;
    int tig  = lane & 3;
    uint32_t sb = (uint32_t)__cvta_generic_to_shared(sm);

    {
        int row = tid >> 1;
        int dh  = (tid & 1) * 32;
        const float* src = g_qc + ((size_t)bn * SS + qbase + row) * DKK + dh;
#pragma unroll
        for (int c = 0; c < 4; c++) {
            float4 f0 = *(const float4*)(src + c * 8);
            float4 f1 = *(const float4*)(src + c * 8 + 4);
            uint32_t h[4], l[4];
            pack_hl(f0.x, f0.y, h[0], l[0]);
            pack_hl(f0.z, f0.w, h[1], l[1]);
            pack_hl(f1.x, f1.y, h[2], l[2]);
            pack_hl(f1.z, f1.w, h[3], l[3]);
            uint32_t off = (uint32_t)(row * APAD + dh + c * 8) * 2;
            *(uint4*)(sm + OFF_QHI + off) = make_uint4(h[0], h[1], h[2], h[3]);
            *(uint4*)(sm + OFF_QLO + off) = make_uint4(l[0], l[1], l[2], l[3]);
        }
    }

    float o[8][4];
#pragma unroll
    for (int i = 0; i < 8; i++)
#pragma unroll
        for (int j = 0; j < 4; j++) o[i][j] = 0.f;
    float l0 = 0.f, l1 = 0.f;

    int q0 = w * 16;
    int arow_q = q0 + (lane & 7) + ((lane >> 3) & 1) * 8;
    int ad_sel = (lane >> 4) * 8;
    int brow   = lane & 7;
    int bsel   = ((lane >> 3) & 1) * 8;

    int ktiles = (cnt + 63) >> 6;
    for (int kt = 0; kt < ktiles; kt++) {
        int kbase = kt * 64;
        __syncthreads();
        {
            int row = tid >> 1;
            int dh  = (tid & 1) * 32;
            const float* ks = g_kc + ((size_t)bn * SS + kbase + row) * DKK + dh;
            const float* vs = g_vc + ((size_t)bn * SS + kbase + row) * DKK + dh;
#pragma unroll
            for (int c = 0; c < 4; c++) {
                float4 f0 = *(const float4*)(ks + c * 8);
                float4 f1 = *(const float4*)(ks + c * 8 + 4);
                uint32_t h[4], l[4];
                pack_hl(f0.x, f0.y, h[0], l[0]);
                pack_hl(f0.z, f0.w, h[1], l[1]);
                pack_hl(f1.x, f1.y, h[2], l[2]);
                pack_hl(f1.z, f1.w, h[3], l[3]);
                uint32_t off = (uint32_t)(row * APAD + dh + c * 8) * 2;
                *(uint4*)(sm + OFF_KHI + off) = make_uint4(h[0], h[1], h[2], h[3]);
                *(uint4*)(sm + OFF_KLO + off) = make_uint4(l[0], l[1], l[2], l[3]);
            }
#pragma unroll
            for (int c = 0; c < 4; c++) {
                float4 f0 = *(const float4*)(vs + c * 8);
                float4 f1 = *(const float4*)(vs + c * 8 + 4);
                uint32_t h[4], l[4];
                pack_hl(f0.x, f0.y, h[0], l[0]);
                pack_hl(f0.z, f0.w, h[1], l[1]);
                pack_hl(f1.x, f1.y, h[2], l[2]);
                pack_hl(f1.z, f1.w, h[3], l[3]);
                uint32_t off = (uint32_t)(row * APAD + dh + c * 8) * 2;
                *(uint4*)(sm + OFF_VHI + off) = make_uint4(h[0], h[1], h[2], h[3]);
                *(uint4*)(sm + OFF_VLO + off) = make_uint4(l[0], l[1], l[2], l[3]);
            }
        }
        __syncthreads();

        float s[8][4];
#pragma unroll
        for (int i = 0; i < 8; i++)
#pragma unroll
            for (int j = 0; j < 4; j++) s[i][j] = 0.f;

#pragma unroll
        for (int c = 0; c < 4; c++) {
            uint32_t aoffq = (uint32_t)(arow_q * APAD + 16 * c + ad_sel) * 2;
            uint32_t ah0, ah1, ah2, ah3, al0, al1, al2, al3;
            ldsm4(ah0, ah1, ah2, ah3, sb + OFF_QHI + aoffq);
            ldsm4(al0, al1, al2, al3, sb + OFF_QLO + aoffq);
#pragma unroll
            for (int j = 0; j < 8; j++) {
                uint32_t boff = (uint32_t)((8 * j + brow) * APAD + 16 * c + bsel) * 2;
                uint32_t bh0, bh1, bl0, bl1;
                ldsm2(bh0, bh1, sb + OFF_KHI + boff);
                ldsm2(bl0, bl1, sb + OFF_KLO + boff);
                mma_bf16(s[j], ah0, ah1, ah2, ah3, bh0, bh1);
                mma_bf16(s[j], al0, al1, al2, al3, bh0, bh1);
                mma_bf16(s[j], ah0, ah1, ah2, ah3, bl0, bl1);
            }
        }

#pragma unroll
        for (int j = 0; j < 8; j++) {
            int kg0 = kbase + 8 * j + 2 * tig;
#pragma unroll
            for (int r = 0; r < 4; r++) {
                int kg = kg0 + (r & 1);
                float p = (kg < cnt) ? __expf(s[j][r] * 0.125f) : 0.f;
                s[j][r] = p;
                if (r < 2) l0 += p; else l1 += p;
            }
        }

#pragma unroll
        for (int c = 0; c < 4; c++) {
            uint32_t ph0, ph1, ph2, ph3, pl0, pl1, pl2, pl3;
            pack_hl(s[2 * c][0],     s[2 * c][1],     ph0, pl0);
            pack_hl(s[2 * c][2],     s[2 * c][3],     ph1, pl1);
            pack_hl(s[2 * c + 1][0], s[2 * c + 1][1], ph2, pl2);
            pack_hl(s[2 * c + 1][2], s[2 * c + 1][3], ph3, pl3);
#pragma unroll
            for (int dt = 0; dt < 8; dt++) {
                uint32_t voff = (uint32_t)((16 * c + bsel + brow) * APAD + 8 * dt) * 2;
                uint32_t vh0, vh1, vl0, vl1;
                ldsm2t(vh0, vh1, sb + OFF_VHI + voff);
                ldsm2t(vl0, vl1, sb + OFF_VLO + voff);
                mma_bf16(o[dt], ph0, ph1, ph2, ph3, vh0, vh1);
                mma_bf16(o[dt], pl0, pl1, pl2, pl3, vh0, vh1);
                mma_bf16(o[dt], ph0, ph1, ph2, ph3, vl0, vl1);
            }
        }
    }

    l0 += __shfl_xor_sync(0xffffffffu, l0, 1);
    l0 += __shfl_xor_sync(0xffffffffu, l0, 2);
    l1 += __shfl_xor_sync(0xffffffffu, l1, 1);
    l1 += __shfl_xor_sync(0xffffffffu, l1, 2);
    float inv0 = 1.0f / l0;
    float inv1 = 1.0f / l1;

    int r0 = qbase + q0 + g;
    int r1 = r0 + 8;
    size_t base0 = ((size_t)b * SS + r0) * HH + n * DKK + 2 * tig;
    size_t base1 = ((size_t)b * SS + r1) * HH + n * DKK + 2 * tig;
#pragma unroll
    for (int dt = 0; dt < 8; dt++) {
        if (r0 < cnt)
            *(float2*)(g_attnc + base0 + 8 * dt) =
                make_float2(o[dt][0] * inv0, o[dt][1] * inv0);
        if (r1 < cnt)
            *(float2*)(g_attnc + base1 + 8 * dt) =
                make_float2(o[dt][2] * inv1, o[dt][3] * inv1);
    }
}

// ---------------- 4) out projection via mma.sync ------------------------------
// grid (8 n-blocks of 64, BB*32 = b*32 + mt -> full 2048 rows), 128 threads
__global__ __launch_bounds__(128)
void outproj_mma_kernel(float* __restrict__ out) {
    int ntb = blockIdx.x;
    int b   = blockIdx.y >> 5;
    int mt  = blockIdx.y & 31;              // 0..31 (64 rows each = 2048)
    int cnt = g_cnt[b];
    if (mt * 64 >= cnt) return;

    __shared__ __align__(16) uint32_t sAhi[64 * 36], sAlo[64 * 36];
    __shared__ __align__(16) uint32_t sWhi[64 * 36], sWlo[64 * 36];

    int tid  = threadIdx.x;
    int w    = tid >> 5;
    int lane = tid & 31;
    int g    = lane >> 2;
    int tig  = lane & 3;
    int arow = w * 16 + (lane & 7) + ((lane >> 3) & 1) * 8;
    int ad   = (lane >> 4) * 8;
    int brow = (lane & 7) + ((lane >> 3) & 1) * 8;

    uint32_t bAhi = (uint32_t)__cvta_generic_to_shared(sAhi);
    uint32_t bAlo = (uint32_t)__cvta_generic_to_shared(sAlo);
    uint32_t bWhi = (uint32_t)__cvta_generic_to_shared(sWhi);
    uint32_t bWlo = (uint32_t)__cvta_generic_to_shared(sWlo);

    float acc[8][4];
#pragma unroll
    for (int i = 0; i < 8; i++)
#pragma unroll
        for (int j = 0; j < 4; j++) acc[i][j] = 0.f;

    int lrow  = tid >> 1;
    int lhalf = (tid & 1) * 16;
    const uint32_t* aH = g_ahi + ((size_t)b * SS + mt * 64 + lrow) * 256 + lhalf;
    const uint32_t* aL = g_alo + ((size_t)b * SS + mt * 64 + lrow) * 256 + lhalf;

    for (int kc = 0; kc < 8; kc++) {
        __syncthreads();
        const uint32_t* wH = g_whi + WO_OFF + (size_t)(kc * 64 + lrow) * 256 + ntb * 32 + lhalf;
        const uint32_t* wL = g_wlo + WO_OFF + (size_t)(kc * 64 + lrow) * 256 + ntb * 32 + lhalf;
#pragma unroll
        for (int j = 0; j < 4; j++) {
            *(uint4*)&sAhi[lrow * 36 + lhalf + 4 * j] = *(const uint4*)(aH + kc * 32 + 4 * j);
            *(uint4*)&sAlo[lrow * 36 + lhalf + 4 * j] = *(const uint4*)(aL + kc * 32 + 4 * j);
            *(uint4*)&sWhi[lrow * 36 + lhalf + 4 * j] = *(const uint4*)(wH + 4 * j);
            *(uint4*)&sWlo[lrow * 36 + lhalf + 4 * j] = *(const uint4*)(wL + 4 * j);
        }
        __syncthreads();
#pragma unroll
        for (int c = 0; c < 4; c++) {
            uint32_t aoff = (uint32_t)(arow * 72 + 16 * c + ad) * 2;
            uint32_t ah0, ah1, ah2, ah3, al0, al1, al2, al3;
            ldsm4(ah0, ah1, ah2, ah3, bAhi + aoff);
            ldsm4(al0, al1, al2, al3, bAlo + aoff);
#pragma unroll
            for (int nt = 0; nt < 8; nt++) {
                uint32_t boff = (uint32_t)((16 * c + brow) * 72 + 8 * nt) * 2;
                uint32_t bh0, bh1, bl0, bl1;
                ldsm2t(bh0, bh1, bWhi + boff);
                ldsm2t(bl0, bl1, bWlo + boff);
                mma_bf16(acc[nt], ah0, ah1, ah2, ah3, bh0, bh1);
                mma_bf16(acc[nt], al0, al1, al2, al3, bh0, bh1);
                mma_bf16(acc[nt], ah0, ah1, ah2, ah3, bl0, bl1);
            }
        }
    }
    int r0 = mt * 64 + w * 16 + g;
    int r1 = r0 + 8;
#pragma unroll
    for (int nt = 0; nt < 8; nt++) {
        int col = ntb * 64 + nt * 8 + 2 * tig;
        if (r0 < cnt) {
            int orig = g_idx[(size_t)b * SS + r0];
            size_t off = ((size_t)b * SS + orig) * HH + col;
            float2 xv = *(const float2*)(g_xn + off);
            *(float2*)(out + off) = make_float2(acc[nt][0] + xv.x, acc[nt][1] + xv.y);
        }
        if (r1 < cnt) {
            int orig = g_idx[(size_t)b * SS + r1];
            size_t off = ((size_t)b * SS + orig) * HH + col;
            float2 xv = *(const float2*)(g_xn + off);
            *(float2*)(out + off) = make_float2(acc[nt][2] + xv.x, acc[nt][3] + xv.y);
        }
    }
}

// ---------------- launch ------------------------------------------------------
extern "C" void kernel_launch(void* const* d_in, const int* in_sizes, int n_in,
                              void* d_out, int out_size) {
    const float* x     = (const float*)d_in[0];
    const int*   mask  = (const int*)  d_in[1];
    const float* Wq    = (const float*)d_in[2];
    const float* Wk    = (const float*)d_in[3];
    const float* Wv    = (const float*)d_in[4];
    const float* Wo    = (const float*)d_in[5];
    const float* gamma = (const float*)d_in[6];
    const float* beta  = (const float*)d_in[7];
    float* out = (float*)d_out;

    cudaFuncSetAttribute(attn_kernel,
                         cudaFuncAttributeMaxDynamicSharedMemorySize, SMA_TOTAL);

    zero_out_kernel<<<(BB * SS * HH) / (256 * 4), 256>>>(out);
    ln_kernel<<<BB * SS, 256>>>(x, gamma, beta);
    compact_kernel<<<BB, 256>>>(mask);
    wcvt_kernel<<<WALL / 256, 256>>>(Wq, Wk, Wv, Wo);
    xcvt_kernel<<<dim3(SS, BB), 128>>>();
    qkv_mma_kernel<<<dim3(32, 96), 128>>>();
    attn_kernel<<<dim3(SS / 64, BB * NH), 128, SMA_TOTAL>>>();
    acvt_kernel<<<dim3(SS, BB), 128>>>();
    outproj_mma_kernel<<<dim3(8, BB * 32), 128>>>(out);
}

// round 10
// speedup vs baseline: 5.4572x; 1.1431x over previous
#include <cuda_runtime.h>
#include <cuda_bf16.h>
#include <math.h>
#include <stdint.h>

#define BB 4
#define SS 2048
#define HH 512
#define NH 8
#define DKK 64

// ---------------- bf16 split + mma.sync helpers (baseline PTX) ---------------
__device__ __forceinline__ uint32_t packbf(float lo, float hi) {
    uint32_t r; asm("cvt.rn.bf16x2.f32 %0, %2, %1;" : "=r"(r) : "f"(lo), "f"(hi)); return r;
}
__device__ __forceinline__ void pack_hl(float e0, float e1, uint32_t& h, uint32_t& l) {
    h = packbf(e0, e1);
    float a = __uint_as_float(h << 16);
    float b = __uint_as_float(h & 0xFFFF0000u);
    l = packbf(e0 - a, e1 - b);
}
__device__ __forceinline__ void ldsm4(uint32_t& r0, uint32_t& r1, uint32_t& r2, uint32_t& r3,
                                      uint32_t a) {
    asm volatile("ldmatrix.sync.aligned.m8n8.x4.shared.b16 {%0,%1,%2,%3}, [%4];"
                 : "=r"(r0), "=r"(r1), "=r"(r2), "=r"(r3) : "r"(a));
}
__device__ __forceinline__ void ldsm2(uint32_t& r0, uint32_t& r1, uint32_t a) {
    asm volatile("ldmatrix.sync.aligned.m8n8.x2.shared.b16 {%0,%1}, [%2];"
                 : "=r"(r0), "=r"(r1) : "r"(a));
}
__device__ __forceinline__ void ldsm2t(uint32_t& r0, uint32_t& r1, uint32_t a) {
    asm volatile("ldmatrix.sync.aligned.m8n8.x2.trans.shared.b16 {%0,%1}, [%2];"
                 : "=r"(r0), "=r"(r1) : "r"(a));
}
__device__ __forceinline__ void mma_bf16(float* c, uint32_t a0, uint32_t a1,
                                         uint32_t a2, uint32_t a3,
                                         uint32_t b0, uint32_t b1) {
    asm volatile(
        "mma.sync.aligned.m16n8k16.row.col.f32.bf16.bf16.f32 "
        "{%0,%1,%2,%3}, {%4,%5,%6,%7}, {%8,%9}, {%0,%1,%2,%3};"
        : "+f"(c[0]), "+f"(c[1]), "+f"(c[2]), "+f"(c[3])
        : "r"(a0), "r"(a1), "r"(a2), "r"(a3), "r"(b0), "r"(b1));
}

// ---------------- scratch ----------------------------------------------------
__device__ float g_xn[BB * SS * HH];          // LN out, fp32, original row order
__device__ int   g_idx[BB * SS];              // compacted pos -> original row
__device__ int   g_rank[BB * SS];             // original row -> compacted pos (-1)
__device__ int   g_cnt[BB];

#define WO_OFF 393216
#define WALL   524288
__device__ uint32_t g_whi[WALL], g_wlo[WALL];
__device__ uint32_t g_xhi[BB * SS * 256], g_xlo[BB * SS * 256];     // compacted xn, bf16 split
__device__ uint32_t g_ahi[BB * SS * 256], g_alo[BB * SS * 256];     // compacted attn out
// q/k/v in bf16 split, 32 u32 per row per (b,n)
__device__ uint32_t g_qhi[BB * NH * SS * 32], g_qlo[BB * NH * SS * 32];
__device__ uint32_t g_khi[BB * NH * SS * 32], g_klo[BB * NH * SS * 32];
__device__ uint32_t g_vhi[BB * NH * SS * 32], g_vlo[BB * NH * SS * 32];

// ---------------- 1) mask compaction + rank map -------------------------------
__global__ void compact_kernel(const int* __restrict__ mask) {
    int b = blockIdx.x;
    int t = threadIdx.x;
    int vals[8];
    int c = 0;
#pragma unroll
    for (int i = 0; i < 8; i++) {
        vals[i] = mask[(size_t)b * SS + t * 8 + i];
        c += (vals[i] != 0);
    }
    __shared__ int s[256];
    s[t] = c;
    __syncthreads();
    for (int off = 1; off < 256; off <<= 1) {
        int v = (t >= off) ? s[t - off] : 0;
        __syncthreads();
        s[t] += v;
        __syncthreads();
    }
    int pos = s[t] - c;
#pragma unroll
    for (int i = 0; i < 8; i++) {
        int orig = t * 8 + i;
        if (vals[i]) {
            g_idx[(size_t)b * SS + pos] = orig;
            g_rank[(size_t)b * SS + orig] = pos;
            pos++;
        } else {
            g_rank[(size_t)b * SS + orig] = -1;
        }
    }
    if (t == 255) g_cnt[b] = s[255];
}

// ---------------- 2) LayerNorm fused with compact-convert + output zeroing ----
// grid BB*SS blocks, 128 threads; thread t owns cols 4t..4t+3 (adjacent).
__global__ void ln_kernel(const float* __restrict__ x,
                          const float* __restrict__ gamma,
                          const float* __restrict__ beta,
                          float* __restrict__ out) {
    int row = blockIdx.x;                 // b*SS + s
    int t = threadIdx.x;
    const float* xr = x + (size_t)row * HH;
    float4 v = *(const float4*)(xr + t * 4);
    float s  = (v.x + v.y) + (v.z + v.w);
    float sq = (v.x * v.x + v.y * v.y) + (v.z * v.z + v.w * v.w);
    __shared__ float ssum[4], ssq[4];
    for (int o = 16; o > 0; o >>= 1) {
        s  += __shfl_xor_sync(0xffffffffu, s,  o);
        sq += __shfl_xor_sync(0xffffffffu, sq, o);
    }
    if ((t & 31) == 0) { ssum[t >> 5] = s; ssq[t >> 5] = sq; }
    __syncthreads();
    float tot  = (ssum[0] + ssum[1]) + (ssum[2] + ssum[3]);
    float totq = (ssq[0]  + ssq[1])  + (ssq[2]  + ssq[3]);
    float mu  = tot * (1.0f / HH);
    float var = totq * (1.0f / HH) - mu * mu;
    float inv = rsqrtf(var + 1e-5f);

    float4 gm = *(const float4*)(gamma + t * 4);
    float4 bt = *(const float4*)(beta  + t * 4);
    float y0 = (v.x - mu) * inv * gm.x + bt.x;
    float y1 = (v.y - mu) * inv * gm.y + bt.y;
    float y2 = (v.z - mu) * inv * gm.z + bt.z;
    float y3 = (v.w - mu) * inv * gm.w + bt.w;

    int rank = g_rank[row];
    if (rank >= 0) {
        *(float4*)(g_xn + (size_t)row * HH + t * 4) = make_float4(y0, y1, y2, y3);
        uint32_t h0, l0, h1, l1;
        pack_hl(y0, y1, h0, l0);
        pack_hl(y2, y3, h1, l1);
        int b = row >> 11;                 // SS = 2048
        size_t o = ((size_t)(b * SS + rank)) * 256 + t * 2;
        g_xhi[o] = h0; g_xhi[o + 1] = h1;
        g_xlo[o] = l0; g_xlo[o + 1] = l1;
    } else {
        *(float4*)(out + (size_t)row * HH + t * 4) = make_float4(0.f, 0.f, 0.f, 0.f);
    }
}

// ---------------- 3) weight convert (fp32 -> bf16 hi/lo) ----------------------
__global__ void wcvt_kernel(const float* __restrict__ Wq, const float* __restrict__ Wk,
                            const float* __restrict__ Wv, const float* __restrict__ Wo) {
    int i = blockIdx.x * 256 + threadIdx.x;       // 0..524287
    const float* src;
    int rem;
    if (i < WO_OFF) {
        int which = i / 131072;
        rem = i - which * 131072;
        src = (which == 0 ? Wq : (which == 1 ? Wk : Wv));
    } else {
        rem = i - WO_OFF;
        src = Wo;
    }
    float2 v = *(const float2*)(src + (size_t)rem * 2);
    uint32_t h, l;
    pack_hl(v.x, v.y, h, l);
    g_whi[i] = h;
    g_wlo[i] = l;
}

// ---------------- 4) QKV projection via mma.sync (bf16 hi/lo output) ----------
// grid (32 m-tiles of 64, 96 = which*32 + bn), 128 threads
__global__ __launch_bounds__(128)
void qkv_mma_kernel() {
    int mt    = blockIdx.x;
    int which = blockIdx.y >> 5;
    int bn    = blockIdx.y & 31;
    int b = bn >> 3, n = bn & 7;
    int cnt = g_cnt[b];
    if (mt * 64 >= cnt) return;

    const uint32_t* Wh = g_whi + which * 131072 + n * 16384;
    const uint32_t* Wl = g_wlo + which * 131072 + n * 16384;
    uint32_t* Ch = (which == 0 ? g_qhi : (which == 1 ? g_khi : g_vhi)) + (size_t)bn * SS * 32;
    uint32_t* Cl = (which == 0 ? g_qlo : (which == 1 ? g_klo : g_vlo)) + (size_t)bn * SS * 32;

    __shared__ __align__(16) uint32_t sAhi[64 * 36], sAlo[64 * 36];
    __shared__ __align__(16) uint32_t sWhi[64 * 36], sWlo[64 * 36];

    int tid  = threadIdx.x;
    int w    = tid >> 5;
    int lane = tid & 31;
    int g    = lane >> 2;
    int tig  = lane & 3;
    int arow = w * 16 + (lane & 7) + ((lane >> 3) & 1) * 8;
    int ad   = (lane >> 4) * 8;
    int brow = (lane & 7) + ((lane >> 3) & 1) * 8;

    uint32_t bAhi = (uint32_t)__cvta_generic_to_shared(sAhi);
    uint32_t bAlo = (uint32_t)__cvta_generic_to_shared(sAlo);
    uint32_t bWhi = (uint32_t)__cvta_generic_to_shared(sWhi);
    uint32_t bWlo = (uint32_t)__cvta_generic_to_shared(sWlo);

    float acc[8][4];
#pragma unroll
    for (int i = 0; i < 8; i++)
#pragma unroll
        for (int j = 0; j < 4; j++) acc[i][j] = 0.f;

    int lrow  = tid >> 1;
    int lhalf = (tid & 1) * 16;
    const uint32_t* aH = g_xhi + ((size_t)b * SS + mt * 64 + lrow) * 256 + lhalf;
    const uint32_t* aL = g_xlo + ((size_t)b * SS + mt * 64 + lrow) * 256 + lhalf;

    for (int kc = 0; kc < 8; kc++) {
        __syncthreads();
        const uint32_t* wH = Wh + (kc * 64 + lrow) * 32 + lhalf;
        const uint32_t* wL = Wl + (kc * 64 + lrow) * 32 + lhalf;
#pragma unroll
        for (int j = 0; j < 4; j++) {
            *(uint4*)&sAhi[lrow * 36 + lhalf + 4 * j] = *(const uint4*)(aH + kc * 32 + 4 * j);
            *(uint4*)&sAlo[lrow * 36 + lhalf + 4 * j] = *(const uint4*)(aL + kc * 32 + 4 * j);
            *(uint4*)&sWhi[lrow * 36 + lhalf + 4 * j] = *(const uint4*)(wH + 4 * j);
            *(uint4*)&sWlo[lrow * 36 + lhalf + 4 * j] = *(const uint4*)(wL + 4 * j);
        }
        __syncthreads();
#pragma unroll
        for (int c = 0; c < 4; c++) {
            uint32_t aoff = (uint32_t)(arow * 72 + 16 * c + ad) * 2;
            uint32_t ah0, ah1, ah2, ah3, al0, al1, al2, al3;
            ldsm4(ah0, ah1, ah2, ah3, bAhi + aoff);
            ldsm4(al0, al1, al2, al3, bAlo + aoff);
#pragma unroll
            for (int nt = 0; nt < 8; nt++) {
                uint32_t boff = (uint32_t)((16 * c + brow) * 72 + 8 * nt) * 2;
                uint32_t bh0, bh1, bl0, bl1;
                ldsm2t(bh0, bh1, bWhi + boff);
                ldsm2t(bl0, bl1, bWlo + boff);
                mma_bf16(acc[nt], ah0, ah1, ah2, ah3, bh0, bh1);
                mma_bf16(acc[nt], al0, al1, al2, al3, bh0, bh1);
                mma_bf16(acc[nt], ah0, ah1, ah2, ah3, bl0, bl1);
            }
        }
    }
    int r0 = mt * 64 + w * 16 + g;
    int r1 = r0 + 8;
#pragma unroll
    for (int nt = 0; nt < 8; nt++) {
        int ci = nt * 4 + tig;                 // u32 column (cols 2ci, 2ci+1)
        if (r0 < cnt) {
            uint32_t h, l;
            pack_hl(acc[nt][0], acc[nt][1], h, l);
            Ch[(size_t)r0 * 32 + ci] = h;
            Cl[(size_t)r0 * 32 + ci] = l;
        }
        if (r1 < cnt) {
            uint32_t h, l;
            pack_hl(acc[nt][2], acc[nt][3], h, l);
            Ch[(size_t)r1 * 32 + ci] = h;
            Cl[(size_t)r1 * 32 + ci] = l;
        }
    }
}

// ---------------- 5) attention: mma.sync bf16-split, pre-converted inputs -----
#define APAD 72
#define OFF_QHI 0
#define OFF_QLO 9216
#define OFF_KHI 18432
#define OFF_KLO 27648
#define OFF_VHI 36864
#define OFF_VLO 46080
#define SMA_TOTAL 55296

__global__ __launch_bounds__(128)
void attn_kernel() {
    extern __shared__ __align__(16) char sm[];
    int bn = blockIdx.y;
    int b  = bn >> 3;
    int n  = bn & 7;
    int cnt = g_cnt[b];
    int qbase = blockIdx.x * 64;
    if (qbase >= cnt) return;

    int tid  = threadIdx.x;
    int w    = tid >> 5;
    int lane = tid & 31;
    int g    = lane >> 2;
    int tig  = lane & 3;
    uint32_t sb = (uint32_t)__cvta_generic_to_shared(sm);

    // ---- stage Q tile: straight uint4 copies (pre-converted) ------------------
    {
        int row   = tid >> 1;
        int half  = tid & 1;                       // 16 u32 per half
        const uint4* qh = (const uint4*)(g_qhi + ((size_t)bn * SS + qbase + row) * 32 + half * 16);
        const uint4* ql = (const uint4*)(g_qlo + ((size_t)bn * SS + qbase + row) * 32 + half * 16);
        uint32_t off = (uint32_t)row * 144 + half * 64;
#pragma unroll
        for (int j = 0; j < 4; j++) {
            *(uint4*)(sm + OFF_QHI + off + j * 16) = qh[j];
            *(uint4*)(sm + OFF_QLO + off + j * 16) = ql[j];
        }
    }

    float o[8][4];
#pragma unroll
    for (int i = 0; i < 8; i++)
#pragma unroll
        for (int j = 0; j < 4; j++) o[i][j] = 0.f;
    float l0 = 0.f, l1 = 0.f;

    int q0 = w * 16;
    int arow_q = q0 + (lane & 7) + ((lane >> 3) & 1) * 8;
    int ad_sel = (lane >> 4) * 8;
    int brow   = lane & 7;
    int bsel   = ((lane >> 3) & 1) * 8;

    int ktiles = (cnt + 63) >> 6;
    for (int kt = 0; kt < ktiles; kt++) {
        int kbase = kt * 64;
        __syncthreads();
        {
            int row  = tid >> 1;
            int half = tid & 1;
            size_t gsrc = ((size_t)bn * SS + kbase + row) * 32 + half * 16;
            const uint4* kh = (const uint4*)(g_khi + gsrc);
            const uint4* kl = (const uint4*)(g_klo + gsrc);
            const uint4* vh = (const uint4*)(g_vhi + gsrc);
            const uint4* vl = (const uint4*)(g_vlo + gsrc);
            uint32_t off = (uint32_t)row * 144 + half * 64;
#pragma unroll
            for (int j = 0; j < 4; j++) {
                *(uint4*)(sm + OFF_KHI + off + j * 16) = kh[j];
                *(uint4*)(sm + OFF_KLO + off + j * 16) = kl[j];
                *(uint4*)(sm + OFF_VHI + off + j * 16) = vh[j];
                *(uint4*)(sm + OFF_VLO + off + j * 16) = vl[j];
            }
        }
        __syncthreads();

        float s[8][4];
#pragma unroll
        for (int i = 0; i < 8; i++)
#pragma unroll
            for (int j = 0; j < 4; j++) s[i][j] = 0.f;

#pragma unroll
        for (int c = 0; c < 4; c++) {
            uint32_t aoffq = (uint32_t)(arow_q * APAD + 16 * c + ad_sel) * 2;
            uint32_t ah0, ah1, ah2, ah3, al0, al1, al2, al3;
            ldsm4(ah0, ah1, ah2, ah3, sb + OFF_QHI + aoffq);
            ldsm4(al0, al1, al2, al3, sb + OFF_QLO + aoffq);
#pragma unroll
            for (int j = 0; j < 8; j++) {
                uint32_t boff = (uint32_t)((8 * j + brow) * APAD + 16 * c + bsel) * 2;
                uint32_t bh0, bh1, bl0, bl1;
                ldsm2(bh0, bh1, sb + OFF_KHI + boff);
                ldsm2(bl0, bl1, sb + OFF_KLO + boff);
                mma_bf16(s[j], ah0, ah1, ah2, ah3, bh0, bh1);
                mma_bf16(s[j], al0, al1, al2, al3, bh0, bh1);
                mma_bf16(s[j], ah0, ah1, ah2, ah3, bl0, bl1);
            }
        }

#pragma unroll
        for (int j = 0; j < 8; j++) {
            int kg0 = kbase + 8 * j + 2 * tig;
#pragma unroll
            for (int r = 0; r < 4; r++) {
                int kg = kg0 + (r & 1);
                float p = (kg < cnt) ? __expf(s[j][r] * 0.125f) : 0.f;
                s[j][r] = p;
                if (r < 2) l0 += p; else l1 += p;
            }
        }

#pragma unroll
        for (int c = 0; c < 4; c++) {
            uint32_t ph0, ph1, ph2, ph3, pl0, pl1, pl2, pl3;
            pack_hl(s[2 * c][0],     s[2 * c][1],     ph0, pl0);
            pack_hl(s[2 * c][2],     s[2 * c][3],     ph1, pl1);
            pack_hl(s[2 * c + 1][0], s[2 * c + 1][1], ph2, pl2);
            pack_hl(s[2 * c + 1][2], s[2 * c + 1][3], ph3, pl3);
#pragma unroll
            for (int dt = 0; dt < 8; dt++) {
                uint32_t voff = (uint32_t)((16 * c + bsel + brow) * APAD + 8 * dt) * 2;
                uint32_t vh0, vh1, vl0, vl1;
                ldsm2t(vh0, vh1, sb + OFF_VHI + voff);
                ldsm2t(vl0, vl1, sb + OFF_VLO + voff);
                mma_bf16(o[dt], ph0, ph1, ph2, ph3, vh0, vh1);
                mma_bf16(o[dt], pl0, pl1, pl2, pl3, vh0, vh1);
                mma_bf16(o[dt], ph0, ph1, ph2, ph3, vl0, vl1);
            }
        }
    }

    l0 += __shfl_xor_sync(0xffffffffu, l0, 1);
    l0 += __shfl_xor_sync(0xffffffffu, l0, 2);
    l1 += __shfl_xor_sync(0xffffffffu, l1, 1);
    l1 += __shfl_xor_sync(0xffffffffu, l1, 2);
    float inv0 = 1.0f / l0;
    float inv1 = 1.0f / l1;

    int r0 = qbase + q0 + g;
    int r1 = r0 + 8;
#pragma unroll
    for (int dt = 0; dt < 8; dt++) {
        int cu = n * 32 + dt * 4 + tig;                // u32 column in 512-col row
        if (r0 < cnt) {
            uint32_t h, l;
            pack_hl(o[dt][0] * inv0, o[dt][1] * inv0, h, l);
            g_ahi[((size_t)b * SS + r0) * 256 + cu] = h;
            g_alo[((size_t)b * SS + r0) * 256 + cu] = l;
        }
        if (r1 < cnt) {
            uint32_t h, l;
            pack_hl(o[dt][2] * inv1, o[dt][3] * inv1, h, l);
            g_ahi[((size_t)b * SS + r1) * 256 + cu] = h;
            g_alo[((size_t)b * SS + r1) * 256 + cu] = l;
        }
    }
}

// ---------------- 6) out projection via mma.sync ------------------------------
// grid (8 n-blocks of 64, BB*32 = b*32 + mt), 128 threads
__global__ __launch_bounds__(128)
void outproj_mma_kernel(float* __restrict__ out) {
    int ntb = blockIdx.x;
    int b   = blockIdx.y >> 5;
    int mt  = blockIdx.y & 31;
    int cnt = g_cnt[b];
    if (mt * 64 >= cnt) return;

    __shared__ __align__(16) uint32_t sAhi[64 * 36], sAlo[64 * 36];
    __shared__ __align__(16) uint32_t sWhi[64 * 36], sWlo[64 * 36];

    int tid  = threadIdx.x;
    int w    = tid >> 5;
    int lane = tid & 31;
    int g    = lane >> 2;
    int tig  = lane & 3;
    int arow = w * 16 + (lane & 7) + ((lane >> 3) & 1) * 8;
    int ad   = (lane >> 4) * 8;
    int brow = (lane & 7) + ((lane >> 3) & 1) * 8;

    uint32_t bAhi = (uint32_t)__cvta_generic_to_shared(sAhi);
    uint32_t bAlo = (uint32_t)__cvta_generic_to_shared(sAlo);
    uint32_t bWhi = (uint32_t)__cvta_generic_to_shared(sWhi);
    uint32_t bWlo = (uint32_t)__cvta_generic_to_shared(sWlo);

    float acc[8][4];
#pragma unroll
    for (int i = 0; i < 8; i++)
#pragma unroll
        for (int j = 0; j < 4; j++) acc[i][j] = 0.f;

    int lrow  = tid >> 1;
    int lhalf = (tid & 1) * 16;
    const uint32_t* aH = g_ahi + ((size_t)b * SS + mt * 64 + lrow) * 256 + lhalf;
    const uint32_t* aL = g_alo + ((size_t)b * SS + mt * 64 + lrow) * 256 + lhalf;

    for (int kc = 0; kc < 8; kc++) {
        __syncthreads();
        const uint32_t* wH = g_whi + WO_OFF + (size_t)(kc * 64 + lrow) * 256 + ntb * 32 + lhalf;
        const uint32_t* wL = g_wlo + WO_OFF + (size_t)(kc * 64 + lrow) * 256 + ntb * 32 + lhalf;
#pragma unroll
        for (int j = 0; j < 4; j++) {
            *(uint4*)&sAhi[lrow * 36 + lhalf + 4 * j] = *(const uint4*)(aH + kc * 32 + 4 * j);
            *(uint4*)&sAlo[lrow * 36 + lhalf + 4 * j] = *(const uint4*)(aL + kc * 32 + 4 * j);
            *(uint4*)&sWhi[lrow * 36 + lhalf + 4 * j] = *(const uint4*)(wH + 4 * j);
            *(uint4*)&sWlo[lrow * 36 + lhalf + 4 * j] = *(const uint4*)(wL + 4 * j);
        }
        __syncthreads();
#pragma unroll
        for (int c = 0; c < 4; c++) {
            uint32_t aoff = (uint32_t)(arow * 72 + 16 * c + ad) * 2;
            uint32_t ah0, ah1, ah2, ah3, al0, al1, al2, al3;
            ldsm4(ah0, ah1, ah2, ah3, bAhi + aoff);
            ldsm4(al0, al1, al2, al3, bAlo + aoff);
#pragma unroll
            for (int nt = 0; nt < 8; nt++) {
                uint32_t boff = (uint32_t)((16 * c + brow) * 72 + 8 * nt) * 2;
                uint32_t bh0, bh1, bl0, bl1;
                ldsm2t(bh0, bh1, bWhi + boff);
                ldsm2t(bl0, bl1, bWlo + boff);
                mma_bf16(acc[nt], ah0, ah1, ah2, ah3, bh0, bh1);
                mma_bf16(acc[nt], al0, al1, al2, al3, bh0, bh1);
                mma_bf16(acc[nt], ah0, ah1, ah2, ah3, bl0, bl1);
            }
        }
    }
    int r0 = mt * 64 + w * 16 + g;
    int r1 = r0 + 8;
#pragma unroll
    for (int nt = 0; nt < 8; nt++) {
        int col = ntb * 64 + nt * 8 + 2 * tig;
        if (r0 < cnt) {
            int orig = g_idx[(size_t)b * SS + r0];
            size_t off = ((size_t)b * SS + orig) * HH + col;
            float2 xv = *(const float2*)(g_xn + off);
            *(float2*)(out + off) = make_float2(acc[nt][0] + xv.x, acc[nt][1] + xv.y);
        }
        if (r1 < cnt) {
            int orig = g_idx[(size_t)b * SS + r1];
            size_t off = ((size_t)b * SS + orig) * HH + col;
            float2 xv = *(const float2*)(g_xn + off);
            *(float2*)(out + off) = make_float2(acc[nt][2] + xv.x, acc[nt][3] + xv.y);
        }
    }
}

// ---------------- launch ------------------------------------------------------
extern "C" void kernel_launch(void* const* d_in, const int* in_sizes, int n_in,
                              void* d_out, int out_size) {
    const float* x     = (const float*)d_in[0];
    const int*   mask  = (const int*)  d_in[1];
    const float* Wq    = (const float*)d_in[2];
    const float* Wk    = (const float*)d_in[3];
    const float* Wv    = (const float*)d_in[4];
    const float* Wo    = (const float*)d_in[5];
    const float* gamma = (const float*)d_in[6];
    const float* beta  = (const float*)d_in[7];
    float* out = (float*)d_out;

    cudaFuncSetAttribute(attn_kernel,
                         cudaFuncAttributeMaxDynamicSharedMemorySize, SMA_TOTAL);

    compact_kernel<<<BB, 256>>>(mask);
    ln_kernel<<<BB * SS, 128>>>(x, gamma, beta, out);
    wcvt_kernel<<<WALL / 256, 256>>>(Wq, Wk, Wv, Wo);
    qkv_mma_kernel<<<dim3(32, 96), 128>>>();
    attn_kernel<<<dim3(SS / 64, BB * NH), 128, SMA_TOTAL>>>();
    outproj_mma_kernel<<<dim3(8, BB * 32), 128>>>(out);
}